// round 2
// baseline (speedup 1.0000x reference)
#include <cuda_runtime.h>
#include <math.h>

#define BB 8
#define NN 4096
#define KK 16
#define CC 64
#define NPTS (BB*NN*KK)
#define EPSF 1e-6f
#define PI_F 3.14159265358979323846f

__device__ double g_mom[34];
__device__ double g_zs1[CC];
__device__ double g_zs2[CC];
__device__ float  g_WcfT[4*CC];
__device__ float  g_bcf[CC];
__device__ float  g_WpfT[5*CC];
__device__ float  g_bpf[CC];
__device__ float  g_WcT[CC*CC];
__device__ float  g_WpT[CC*CC];
__device__ float  g_bz[CC];
__device__ float  g_bp[CC];
__device__ float  g_W2T[CC*CC];
__device__ float  g_alpha[CC];
__device__ float  g_beta[CC];
__device__ float4 g_z1[16*NPTS];

__device__ __forceinline__ float wsum32(float v){
#pragma unroll
    for (int m=1; m<32; m<<=1) v += __shfl_xor_sync(0xffffffffu, v, m);
    return v;
}
__device__ __forceinline__ float gsum16(float v){
#pragma unroll
    for (int m=1; m<16; m<<=1) v += __shfl_xor_sync(0xffffffffu, v, m);
    return v;
}
__device__ __forceinline__ int clampi(int x,int lo,int hi){return x<lo?lo:(x>hi?hi:x);}

struct Geo {
    float dx,dy,dz,r,rn,sth,cth,sph,cph,theta;
};
__device__ __forceinline__ Geo geom(const float* __restrict__ nxyz,
                                    const float* __restrict__ cxyz, int p){
    int b = p>>16, n = (p>>4)&(NN-1), k = p&(KK-1);
    int cb = (b*3)*NN + n;
    float cx=cxyz[cb], cy=cxyz[cb+NN], cz=cxyz[cb+2*NN];
    int nb = ((b*3)*NN + n)*KK + k;
    Geo g;
    g.dx = nxyz[nb]           - cx;
    g.dy = nxyz[nb+NN*KK]     - cy;
    g.dz = nxyz[nb+2*NN*KK]   - cz;
    float r = sqrtf(g.dx*g.dx + g.dy*g.dy + g.dz*g.dz); r = fmaxf(r, EPSF);
    float rho = fmaxf(sqrtf(g.dx*g.dx + g.dy*g.dy), EPSF);
    g.r = r;
    g.theta = atan2f(g.dy, g.dx);
    float phi = atan2f(g.dz, rho);
    float rmean = gsum16(r) * (1.0f/16.0f);
    g.rn = fminf(r/(rmean+EPSF), 3.0f) * (1.0f/3.0f);
    sincosf(g.theta, &g.sth, &g.cth);
    sincosf(phi, &g.sph, &g.cph);
    return g;
}

__global__ void zero_kernel(){
    int t = threadIdx.x;
    if (t < 34) g_mom[t] = 0.0;
    if (t < CC) { g_zs1[t]=0.0; g_zs2[t]=0.0; }
}

__global__ __launch_bounds__(256) void moments_kernel(const float* __restrict__ nxyz,
                                                      const float* __restrict__ cxyz){
    __shared__ double smom[34];
    int tid = threadIdx.x;
    if (tid < 34) smom[tid] = 0.0;
    __syncthreads();
    int p = blockIdx.x*256 + tid;
    Geo g = geom(nxyz, cxyz, p);
    float fc[4] = {g.dx, g.dy, g.dz, g.r};
    float fp[5] = {g.rn, g.sth, g.cth, g.sph, g.cph};
    float v[34];
#pragma unroll
    for (int i=0;i<4;i++){
        v[i] = fc[i];
#pragma unroll
        for (int j=i;j<4;j++) v[4 + i*4 - (i*(i-1))/2 + (j-i)] = fc[i]*fc[j];
    }
#pragma unroll
    for (int i=0;i<5;i++){
        v[14+i] = fp[i];
#pragma unroll
        for (int j=i;j<5;j++) v[19 + i*5 - (i*(i-1))/2 + (j-i)] = fp[i]*fp[j];
    }
#pragma unroll
    for (int i=0;i<34;i++){
        float s = wsum32(v[i]);
        if ((tid&31)==0) atomicAdd(&smom[i], (double)s);
    }
    __syncthreads();
    if (tid < 34) atomicAdd(&g_mom[tid], smom[tid]);
}

__global__ void setup_kernel(
    const float* __restrict__ cf_w1, const float* __restrict__ cf_b1,
    const float* __restrict__ cf_g,  const float* __restrict__ cf_be,
    const float* __restrict__ cf_w2, const float* __restrict__ cf_b2,
    const float* __restrict__ pf_w1, const float* __restrict__ pf_b1,
    const float* __restrict__ pf_g,  const float* __restrict__ pf_be,
    const float* __restrict__ pf_w2, const float* __restrict__ pf_b2,
    const float* __restrict__ ac_w,  const float* __restrict__ ac_b,
    const float* __restrict__ ap_w,  const float* __restrict__ ap_b,
    const float* __restrict__ gamma_p,
    const float* __restrict__ ge_w1, const float* __restrict__ ge_b1,
    const float* __restrict__ ge_w2)
{
    __shared__ float sT[CC*CC];
    __shared__ float sv1[CC], sv2[CC];
    int tid = threadIdx.x;
    float gam = gamma_p[0];
    const double inv = 1.0/(double)NPTS;

    if (tid < CC){
        { // cart BN fold
            double mu[4], cov[4][4];
#pragma unroll
            for (int i=0;i<4;i++) mu[i] = g_mom[i]*inv;
#pragma unroll
            for (int i=0;i<4;i++)
#pragma unroll
                for (int j=i;j<4;j++){
                    double c2 = g_mom[4 + i*4 - (i*(i-1))/2 + (j-i)]*inv - mu[i]*mu[j];
                    cov[i][j]=c2; cov[j][i]=c2;
                }
            double w[4], m=(double)cf_b1[tid], vv=0.0;
#pragma unroll
            for (int i=0;i<4;i++){ w[i]=(double)cf_w1[tid*4+i]; m += w[i]*mu[i]; }
#pragma unroll
            for (int i=0;i<4;i++)
#pragma unroll
                for (int j=0;j<4;j++) vv += w[i]*w[j]*cov[i][j];
            double al = (double)cf_g[tid]/sqrt(vv+1e-5);
#pragma unroll
            for (int i=0;i<4;i++) g_WcfT[i*CC+tid] = (float)(w[i]*al);
            g_bcf[tid] = (float)(((double)cf_b1[tid]-m)*al + (double)cf_be[tid]);
        }
        { // polar BN fold
            double mu[5], cov[5][5];
#pragma unroll
            for (int i=0;i<5;i++) mu[i] = g_mom[14+i]*inv;
#pragma unroll
            for (int i=0;i<5;i++)
#pragma unroll
                for (int j=i;j<5;j++){
                    double c2 = g_mom[19 + i*5 - (i*(i-1))/2 + (j-i)]*inv - mu[i]*mu[j];
                    cov[i][j]=c2; cov[j][i]=c2;
                }
            double w[5], m=(double)pf_b1[tid], vv=0.0;
#pragma unroll
            for (int i=0;i<5;i++){ w[i]=(double)pf_w1[tid*5+i]; m += w[i]*mu[i]; }
#pragma unroll
            for (int i=0;i<5;i++)
#pragma unroll
                for (int j=0;j<5;j++) vv += w[i]*w[j]*cov[i][j];
            double al = (double)pf_g[tid]/sqrt(vv+1e-5);
#pragma unroll
            for (int i=0;i<5;i++) g_WpfT[i*CC+tid] = (float)(w[i]*al);
            g_bpf[tid] = (float)(((double)pf_b1[tid]-m)*al + (double)pf_be[tid]);
        }
    }
    // T1 = ac_w @ cf_w2 ; Wc = ge_w1 @ T1 (stored transposed)
    for (int e=tid;e<CC*CC;e+=blockDim.x){
        int m=e>>6, j=e&63; float s=0.f;
        for (int l=0;l<CC;l++) s += ac_w[m*CC+l]*cf_w2[l*CC+j];
        sT[e]=s;
    }
    __syncthreads();
    for (int e=tid;e<CC*CC;e+=blockDim.x){
        int c=e>>6, j=e&63; float s=0.f;
        for (int m=0;m<CC;m++) s += ge_w1[c*CC+m]*sT[m*CC+j];
        g_WcT[j*CC+c]=s;
    }
    __syncthreads();
    // T2 = ap_w @ pf_w2 ; Wp = gamma * ge_w1 @ T2 (transposed)
    for (int e=tid;e<CC*CC;e+=blockDim.x){
        int m=e>>6, j=e&63; float s=0.f;
        for (int l=0;l<CC;l++) s += ap_w[m*CC+l]*pf_w2[l*CC+j];
        sT[e]=s;
    }
    __syncthreads();
    for (int e=tid;e<CC*CC;e+=blockDim.x){
        int c=e>>6, j=e&63; float s=0.f;
        for (int m=0;m<CC;m++) s += ge_w1[c*CC+m]*sT[m*CC+j];
        g_WpT[j*CC+c]=gam*s;
    }
    // bias vectors
    if (tid < CC){
        float s1 = ac_b[tid] + gam*ap_b[tid];
        for (int j=0;j<CC;j++) s1 += ac_w[tid*CC+j]*cf_b2[j];
        sv1[tid]=s1;
        float s2 = 0.f;
        for (int j=0;j<CC;j++) s2 += ap_w[tid*CC+j]*pf_b2[j];
        sv2[tid]=s2;
    }
    __syncthreads();
    if (tid < CC){
        float bz = ge_b1[tid], bp = 0.f;
        for (int m=0;m<CC;m++){ bz += ge_w1[tid*CC+m]*sv1[m]; bp += ge_w1[tid*CC+m]*sv2[m]; }
        g_bz[tid]=bz; g_bp[tid]=gam*bp;
    }
    for (int e=tid;e<CC*CC;e+=blockDim.x) g_W2T[(e&63)*CC + (e>>6)] = ge_w2[e];
}

__global__ __launch_bounds__(256,1) void main_kernel(const float* __restrict__ nxyz,
                                                     const float* __restrict__ cxyz){
    __shared__ float sWcT[CC*CC];
    __shared__ float sWpT[CC*CC];
    __shared__ float sWcf[4*CC], sWpf[5*CC];
    __shared__ float sbcf[CC], sbpf[CC], sbz[CC], sbp[CC];
    __shared__ double sS1[CC], sS2[CC];
    int tid = threadIdx.x;
    for (int i=tid;i<CC*CC;i+=256){ sWcT[i]=g_WcT[i]; sWpT[i]=g_WpT[i]; }
    for (int i=tid;i<4*CC;i+=256) sWcf[i]=g_WcfT[i];
    for (int i=tid;i<5*CC;i+=256) sWpf[i]=g_WpfT[i];
    if (tid < CC){
        sbcf[tid]=g_bcf[tid]; sbpf[tid]=g_bpf[tid];
        sbz[tid]=g_bz[tid];   sbp[tid]=g_bp[tid];
        sS1[tid]=0.0; sS2[tid]=0.0;
    }
    __syncthreads();

    int p = blockIdx.x*256 + tid;
    Geo g = geom(nxyz, cxyz, p);

    // bilinear bins
    float ridx = g.rn*(2.0f - 1e-6f);
    float aidx = ((g.theta + PI_F)*(0.5f/PI_F))*(12.0f - 1e-6f);
    float ri0f = floorf(ridx); float rw1 = ridx-ri0f, rw0 = 1.0f-rw1;
    int ri0 = clampi((int)ri0f,0,1), ri1 = clampi((int)ri0f+1,0,1);
    float ai0f = floorf(aidx); float aw1 = aidx-ai0f, aw0 = 1.0f-aw1;
    int ai0 = clampi((int)ai0f,0,11), ai1 = clampi((int)ai0f+1,0,11);
    float w00=rw0*aw0, w01=rw0*aw1, w10=rw1*aw0, w11=rw1*aw1;
    int c00=ri0*12+ai0, c01=ri0*12+ai1, c10=ri1*12+ai0, c11=ri1*12+ai1;

    int t0 = __shfl_sync(0xffffffffu, c00, 0, 16);
    int t1 = __shfl_sync(0xffffffffu, c01, 0, 16);
    int t2 = __shfl_sync(0xffffffffu, c10, 0, 16);
    int t3 = __shfl_sync(0xffffffffu, c11, 0, 16);

    float coef0 = (c00==t0?w00:0.f)+(c01==t0?w01:0.f)+(c10==t0?w10:0.f)+(c11==t0?w11:0.f);
    float coef1 = (c00==t1?w00:0.f)+(c01==t1?w01:0.f)+(c10==t1?w10:0.f)+(c11==t1?w11:0.f);
    float coef2 = (c00==t2?w00:0.f)+(c01==t2?w01:0.f)+(c10==t2?w10:0.f)+(c11==t2?w11:0.f);
    float coef3 = (c00==t3?w00:0.f)+(c01==t3?w01:0.f)+(c10==t3?w10:0.f)+(c11==t3?w11:0.f);

    float den0 = gsum16(coef0), den1 = gsum16(coef1);
    float den2 = gsum16(coef2), den3 = gsum16(coef3);
    float m0 = w00/fmaxf(den0,EPSF), m1 = w01/fmaxf(den1,EPSF);
    float m2 = w10/fmaxf(den2,EPSF), m3 = w11/fmaxf(den3,EPSF);
    float s_k = m0*den0 + m1*den1 + m2*den2 + m3*den3;

    float4 acc[16];
#pragma unroll
    for (int c4=0;c4<16;c4++){
        float4 bz4 = ((const float4*)sbz)[c4];
        float4 bp4 = ((const float4*)sbp)[c4];
        acc[c4].x = fmaf(bp4.x, s_k, bz4.x);
        acc[c4].y = fmaf(bp4.y, s_k, bz4.y);
        acc[c4].z = fmaf(bp4.z, s_k, bz4.z);
        acc[c4].w = fmaf(bp4.w, s_k, bz4.w);
    }

    // cart branch
#pragma unroll 2
    for (int j=0;j<CC;j++){
        float hj = sbcf[j];
        hj = fmaf(g.dx, sWcf[j],        hj);
        hj = fmaf(g.dy, sWcf[CC+j],     hj);
        hj = fmaf(g.dz, sWcf[2*CC+j],   hj);
        hj = fmaf(g.r,  sWcf[3*CC+j],   hj);
        hj = fmaxf(hj, 0.0f);
        const float4* wr = (const float4*)(sWcT + j*CC);
#pragma unroll
        for (int c4=0;c4<16;c4++){
            float4 w = wr[c4];
            acc[c4].x = fmaf(w.x,hj,acc[c4].x);
            acc[c4].y = fmaf(w.y,hj,acc[c4].y);
            acc[c4].z = fmaf(w.z,hj,acc[c4].z);
            acc[c4].w = fmaf(w.w,hj,acc[c4].w);
        }
    }
    // polar branch with k-mix
#pragma unroll 1
    for (int j=0;j<CC;j++){
        float hj = sbpf[j];
        hj = fmaf(g.rn,  sWpf[j],      hj);
        hj = fmaf(g.sth, sWpf[CC+j],   hj);
        hj = fmaf(g.cth, sWpf[2*CC+j], hj);
        hj = fmaf(g.sph, sWpf[3*CC+j], hj);
        hj = fmaf(g.cph, sWpf[4*CC+j], hj);
        hj = fmaxf(hj, 0.0f);
        float g0 = coef0*hj, g1 = coef1*hj, g2 = coef2*hj, g3 = coef3*hj;
#pragma unroll
        for (int m=1;m<16;m<<=1){
            g0 += __shfl_xor_sync(0xffffffffu, g0, m);
            g1 += __shfl_xor_sync(0xffffffffu, g1, m);
            g2 += __shfl_xor_sync(0xffffffffu, g2, m);
            g3 += __shfl_xor_sync(0xffffffffu, g3, m);
        }
        float hm = m0*g0 + m1*g1 + m2*g2 + m3*g3;
        const float4* wr = (const float4*)(sWpT + j*CC);
#pragma unroll
        for (int c4=0;c4<16;c4++){
            float4 w = wr[c4];
            acc[c4].x = fmaf(w.x,hm,acc[c4].x);
            acc[c4].y = fmaf(w.y,hm,acc[c4].y);
            acc[c4].z = fmaf(w.z,hm,acc[c4].z);
            acc[c4].w = fmaf(w.w,hm,acc[c4].w);
        }
    }
#pragma unroll
    for (int c4=0;c4<16;c4++) g_z1[c4*NPTS + p] = acc[c4];

    // BN3 moments
#pragma unroll
    for (int c4=0;c4<16;c4++){
        float vs[4] = {acc[c4].x, acc[c4].y, acc[c4].z, acc[c4].w};
#pragma unroll
        for (int q=0;q<4;q++){
            float s1 = wsum32(vs[q]);
            float s2 = wsum32(vs[q]*vs[q]);
            if ((tid&31)==0){ atomicAdd(&sS1[4*c4+q],(double)s1); atomicAdd(&sS2[4*c4+q],(double)s2); }
        }
    }
    __syncthreads();
    if (tid < CC){ atomicAdd(&g_zs1[tid], sS1[tid]); atomicAdd(&g_zs2[tid], sS2[tid]); }
}

__global__ void bnstats_kernel(const float* __restrict__ ge_g, const float* __restrict__ ge_be){
    int c = threadIdx.x;
    if (c < CC){
        double mean = g_zs1[c]/(double)NPTS;
        double var  = g_zs2[c]/(double)NPTS - mean*mean;
        double a = (double)ge_g[c]/sqrt(var + 1e-5);
        g_alpha[c] = (float)a;
        g_beta[c]  = (float)((double)ge_be[c] - mean*a);
    }
}

__global__ __launch_bounds__(256,1) void final_kernel(const float* __restrict__ ge_b2,
                                                      float* __restrict__ out){
    __shared__ float sW[CC*CC];
    __shared__ float sa[CC], sbv[CC], sb2[CC];
    int tid = threadIdx.x;
    for (int i=tid;i<CC*CC;i+=256) sW[i]=g_W2T[i];
    if (tid < CC){ sa[tid]=g_alpha[tid]; sbv[tid]=g_beta[tid]; sb2[tid]=ge_b2[tid]; }
    __syncthreads();

    int p = blockIdx.x*256 + tid;
    float4 acc[16];
#pragma unroll
    for (int c4=0;c4<16;c4++){
        float4 b4 = ((const float4*)sb2)[c4];
        acc[c4] = b4;
    }
#pragma unroll 2
    for (int j4=0;j4<16;j4++){
        float4 z4 = g_z1[j4*NPTS + p];
        float4 a4 = ((const float4*)sa)[j4];
        float4 bb4 = ((const float4*)sbv)[j4];
        float h[4];
        h[0] = fmaxf(fmaf(z4.x, a4.x, bb4.x), 0.0f);
        h[1] = fmaxf(fmaf(z4.y, a4.y, bb4.y), 0.0f);
        h[2] = fmaxf(fmaf(z4.z, a4.z, bb4.z), 0.0f);
        h[3] = fmaxf(fmaf(z4.w, a4.w, bb4.w), 0.0f);
#pragma unroll
        for (int q=0;q<4;q++){
            int j = j4*4 + q;
            const float4* wr = (const float4*)(sW + j*CC);
            float hj = h[q];
#pragma unroll
            for (int c4=0;c4<16;c4++){
                float4 w = wr[c4];
                acc[c4].x = fmaf(w.x,hj,acc[c4].x);
                acc[c4].y = fmaf(w.y,hj,acc[c4].y);
                acc[c4].z = fmaf(w.z,hj,acc[c4].z);
                acc[c4].w = fmaf(w.w,hj,acc[c4].w);
            }
        }
    }
    int b = p>>16, nk = p & 65535;
    float* ob = out + (size_t)b*CC*NN*KK + nk;
#pragma unroll
    for (int c4=0;c4<16;c4++){
        ob[(size_t)(4*c4+0)*NN*KK] = acc[c4].x;
        ob[(size_t)(4*c4+1)*NN*KK] = acc[c4].y;
        ob[(size_t)(4*c4+2)*NN*KK] = acc[c4].z;
        ob[(size_t)(4*c4+3)*NN*KK] = acc[c4].w;
    }
}

extern "C" void kernel_launch(void* const* d_in, const int* in_sizes, int n_in,
                              void* d_out, int out_size){
    const float* nxyz  = (const float*)d_in[0];
    const float* cxyz  = (const float*)d_in[1];
    const float* cf_w1 = (const float*)d_in[2];
    const float* cf_b1 = (const float*)d_in[3];
    const float* cf_g  = (const float*)d_in[4];
    const float* cf_be = (const float*)d_in[5];
    const float* cf_w2 = (const float*)d_in[6];
    const float* cf_b2 = (const float*)d_in[7];
    const float* pf_w1 = (const float*)d_in[8];
    const float* pf_b1 = (const float*)d_in[9];
    const float* pf_g  = (const float*)d_in[10];
    const float* pf_be = (const float*)d_in[11];
    const float* pf_w2 = (const float*)d_in[12];
    const float* pf_b2 = (const float*)d_in[13];
    const float* ac_w  = (const float*)d_in[14];
    const float* ac_b  = (const float*)d_in[15];
    const float* ap_w  = (const float*)d_in[16];
    const float* ap_b  = (const float*)d_in[17];
    const float* gamma = (const float*)d_in[18];
    const float* ge_w1 = (const float*)d_in[19];
    const float* ge_b1 = (const float*)d_in[20];
    const float* ge_g  = (const float*)d_in[21];
    const float* ge_be = (const float*)d_in[22];
    const float* ge_w2 = (const float*)d_in[23];
    const float* ge_b2 = (const float*)d_in[24];
    float* out = (float*)d_out;

    zero_kernel<<<1, 64>>>();
    moments_kernel<<<NPTS/256, 256>>>(nxyz, cxyz);
    setup_kernel<<<1, 256>>>(cf_w1, cf_b1, cf_g, cf_be, cf_w2, cf_b2,
                             pf_w1, pf_b1, pf_g, pf_be, pf_w2, pf_b2,
                             ac_w, ac_b, ap_w, ap_b, gamma,
                             ge_w1, ge_b1, ge_w2);
    main_kernel<<<NPTS/256, 256>>>(nxyz, cxyz);
    bnstats_kernel<<<1, 64>>>(ge_g, ge_be);
    final_kernel<<<NPTS/256, 256>>>(ge_b2, out);
}

// round 3
// speedup vs baseline: 1.2314x; 1.2314x over previous
#include <cuda_runtime.h>
#include <math.h>

#define BB 8
#define NN 4096
#define KK 16
#define CC 64
#define NPTS (BB*NN*KK)
#define EPSF 1e-6f
#define PI_F 3.14159265358979323846f

__device__ double g_mom[34];
__device__ double g_zs1[CC];
__device__ double g_zs2[CC];
__device__ float  g_WcfT[4*CC];
__device__ float  g_bcf[CC];
__device__ float  g_WpfT[5*CC];
__device__ float  g_bpf[CC];
__device__ float  g_WcT[CC*CC];
__device__ float  g_WpT[CC*CC];
__device__ float  g_bz[CC];
__device__ float  g_bp[CC];
__device__ float  g_W2T[CC*CC];
__device__ float  g_alpha[CC];
__device__ float  g_beta[CC];
__device__ float4 g_z1[16*NPTS];

__device__ __forceinline__ float wsum32(float v){
#pragma unroll
    for (int m=1; m<32; m<<=1) v += __shfl_xor_sync(0xffffffffu, v, m);
    return v;
}
__device__ __forceinline__ float gsum16(float v){
#pragma unroll
    for (int m=1; m<16; m<<=1) v += __shfl_xor_sync(0xffffffffu, v, m);
    return v;
}
__device__ __forceinline__ int clampi(int x,int lo,int hi){return x<lo?lo:(x>hi?hi:x);}

struct Geo { float dx,dy,dz,r,rn,sth,cth,sph,cph,theta; };

__device__ __forceinline__ Geo geom(const float* __restrict__ nxyz,
                                    const float* __restrict__ cxyz, int p){
    int b = p>>16, n = (p>>4)&(NN-1), k = p&(KK-1);
    int cb = (b*3)*NN + n;
    float cx=cxyz[cb], cy=cxyz[cb+NN], cz=cxyz[cb+2*NN];
    int nb = ((b*3)*NN + n)*KK + k;
    Geo g;
    g.dx = nxyz[nb]           - cx;
    g.dy = nxyz[nb+NN*KK]     - cy;
    g.dz = nxyz[nb+2*NN*KK]   - cz;
    float r = sqrtf(g.dx*g.dx + g.dy*g.dy + g.dz*g.dz); r = fmaxf(r, EPSF);
    float rho = fmaxf(sqrtf(g.dx*g.dx + g.dy*g.dy), EPSF);
    g.r = r;
    g.theta = atan2f(g.dy, g.dx);
    float phi = atan2f(g.dz, rho);
    float rmean = gsum16(r) * (1.0f/16.0f);
    g.rn = fminf(r/(rmean+EPSF), 3.0f) * (1.0f/3.0f);
    sincosf(g.theta, &g.sth, &g.cth);
    sincosf(phi, &g.sph, &g.cph);
    return g;
}

struct Mix { float c0,c1,c2,c3, m0,m1,m2,m3, s_k; };

__device__ __forceinline__ Mix make_mix(const Geo& g){
    float ridx = g.rn*(2.0f - 1e-6f);
    float aidx = ((g.theta + PI_F)*(0.5f/PI_F))*(12.0f - 1e-6f);
    float ri0f = floorf(ridx); float rw1 = ridx-ri0f, rw0 = 1.0f-rw1;
    int ri0 = clampi((int)ri0f,0,1), ri1 = clampi((int)ri0f+1,0,1);
    float ai0f = floorf(aidx); float aw1 = aidx-ai0f, aw0 = 1.0f-aw1;
    int ai0 = clampi((int)ai0f,0,11), ai1 = clampi((int)ai0f+1,0,11);
    float w00=rw0*aw0, w01=rw0*aw1, w10=rw1*aw0, w11=rw1*aw1;
    int c00=ri0*12+ai0, c01=ri0*12+ai1, c10=ri1*12+ai0, c11=ri1*12+ai1;

    int t0 = __shfl_sync(0xffffffffu, c00, 0, 16);
    int t1 = __shfl_sync(0xffffffffu, c01, 0, 16);
    int t2 = __shfl_sync(0xffffffffu, c10, 0, 16);
    int t3 = __shfl_sync(0xffffffffu, c11, 0, 16);

    Mix mx;
    mx.c0 = (c00==t0?w00:0.f)+(c01==t0?w01:0.f)+(c10==t0?w10:0.f)+(c11==t0?w11:0.f);
    mx.c1 = (c00==t1?w00:0.f)+(c01==t1?w01:0.f)+(c10==t1?w10:0.f)+(c11==t1?w11:0.f);
    mx.c2 = (c00==t2?w00:0.f)+(c01==t2?w01:0.f)+(c10==t2?w10:0.f)+(c11==t2?w11:0.f);
    mx.c3 = (c00==t3?w00:0.f)+(c01==t3?w01:0.f)+(c10==t3?w10:0.f)+(c11==t3?w11:0.f);

    float den0 = gsum16(mx.c0), den1 = gsum16(mx.c1);
    float den2 = gsum16(mx.c2), den3 = gsum16(mx.c3);
    mx.m0 = w00/fmaxf(den0,EPSF); mx.m1 = w01/fmaxf(den1,EPSF);
    mx.m2 = w10/fmaxf(den2,EPSF); mx.m3 = w11/fmaxf(den3,EPSF);
    mx.s_k = mx.m0*den0 + mx.m1*den1 + mx.m2*den2 + mx.m3*den3;
    return mx;
}

// apply the 16x16 k-mix to one scalar channel (independent chains -> high ILP)
__device__ __forceinline__ float mix16(float v, const Mix& mx){
    float g0 = mx.c0*v, g1 = mx.c1*v, g2 = mx.c2*v, g3 = mx.c3*v;
#pragma unroll
    for (int m=1;m<16;m<<=1){
        g0 += __shfl_xor_sync(0xffffffffu, g0, m);
        g1 += __shfl_xor_sync(0xffffffffu, g1, m);
        g2 += __shfl_xor_sync(0xffffffffu, g2, m);
        g3 += __shfl_xor_sync(0xffffffffu, g3, m);
    }
    return mx.m0*g0 + mx.m1*g1 + mx.m2*g2 + mx.m3*g3;
}

__global__ void zero_kernel(){
    int t = threadIdx.x;
    if (t < 34) g_mom[t] = 0.0;
    if (t < CC) { g_zs1[t]=0.0; g_zs2[t]=0.0; }
}

__global__ __launch_bounds__(256) void moments_kernel(const float* __restrict__ nxyz,
                                                      const float* __restrict__ cxyz){
    __shared__ double smom[34];
    int tid = threadIdx.x;
    if (tid < 34) smom[tid] = 0.0;
    __syncthreads();
    int p = blockIdx.x*256 + tid;
    Geo g = geom(nxyz, cxyz, p);
    float fc[4] = {g.dx, g.dy, g.dz, g.r};
    float fp[5] = {g.rn, g.sth, g.cth, g.sph, g.cph};
    float v[34];
#pragma unroll
    for (int i=0;i<4;i++){
        v[i] = fc[i];
#pragma unroll
        for (int j=i;j<4;j++) v[4 + i*4 - (i*(i-1))/2 + (j-i)] = fc[i]*fc[j];
    }
#pragma unroll
    for (int i=0;i<5;i++){
        v[14+i] = fp[i];
#pragma unroll
        for (int j=i;j<5;j++) v[19 + i*5 - (i*(i-1))/2 + (j-i)] = fp[i]*fp[j];
    }
#pragma unroll
    for (int i=0;i<34;i++){
        float s = wsum32(v[i]);
        if ((tid&31)==0) atomicAdd(&smom[i], (double)s);
    }
    __syncthreads();
    if (tid < 34) atomicAdd(&g_mom[tid], smom[tid]);
}

__global__ void setup_kernel(
    const float* __restrict__ cf_w1, const float* __restrict__ cf_b1,
    const float* __restrict__ cf_g,  const float* __restrict__ cf_be,
    const float* __restrict__ cf_w2, const float* __restrict__ cf_b2,
    const float* __restrict__ pf_w1, const float* __restrict__ pf_b1,
    const float* __restrict__ pf_g,  const float* __restrict__ pf_be,
    const float* __restrict__ pf_w2, const float* __restrict__ pf_b2,
    const float* __restrict__ ac_w,  const float* __restrict__ ac_b,
    const float* __restrict__ ap_w,  const float* __restrict__ ap_b,
    const float* __restrict__ gamma_p,
    const float* __restrict__ ge_w1, const float* __restrict__ ge_b1,
    const float* __restrict__ ge_w2)
{
    __shared__ float sT[CC*CC];
    __shared__ float sv1[CC], sv2[CC];
    int tid = threadIdx.x;
    float gam = gamma_p[0];
    const double inv = 1.0/(double)NPTS;

    if (tid < CC){
        { // cart BN fold
            double mu[4], cov[4][4];
#pragma unroll
            for (int i=0;i<4;i++) mu[i] = g_mom[i]*inv;
#pragma unroll
            for (int i=0;i<4;i++)
#pragma unroll
                for (int j=i;j<4;j++){
                    double c2 = g_mom[4 + i*4 - (i*(i-1))/2 + (j-i)]*inv - mu[i]*mu[j];
                    cov[i][j]=c2; cov[j][i]=c2;
                }
            double w[4], m=(double)cf_b1[tid], vv=0.0;
#pragma unroll
            for (int i=0;i<4;i++){ w[i]=(double)cf_w1[tid*4+i]; m += w[i]*mu[i]; }
#pragma unroll
            for (int i=0;i<4;i++)
#pragma unroll
                for (int j=0;j<4;j++) vv += w[i]*w[j]*cov[i][j];
            double al = (double)cf_g[tid]/sqrt(vv+1e-5);
#pragma unroll
            for (int i=0;i<4;i++) g_WcfT[i*CC+tid] = (float)(w[i]*al);
            g_bcf[tid] = (float)(((double)cf_b1[tid]-m)*al + (double)cf_be[tid]);
        }
        { // polar BN fold
            double mu[5], cov[5][5];
#pragma unroll
            for (int i=0;i<5;i++) mu[i] = g_mom[14+i]*inv;
#pragma unroll
            for (int i=0;i<5;i++)
#pragma unroll
                for (int j=i;j<5;j++){
                    double c2 = g_mom[19 + i*5 - (i*(i-1))/2 + (j-i)]*inv - mu[i]*mu[j];
                    cov[i][j]=c2; cov[j][i]=c2;
                }
            double w[5], m=(double)pf_b1[tid], vv=0.0;
#pragma unroll
            for (int i=0;i<5;i++){ w[i]=(double)pf_w1[tid*5+i]; m += w[i]*mu[i]; }
#pragma unroll
            for (int i=0;i<5;i++)
#pragma unroll
                for (int j=0;j<5;j++) vv += w[i]*w[j]*cov[i][j];
            double al = (double)pf_g[tid]/sqrt(vv+1e-5);
#pragma unroll
            for (int i=0;i<5;i++) g_WpfT[i*CC+tid] = (float)(w[i]*al);
            g_bpf[tid] = (float)(((double)pf_b1[tid]-m)*al + (double)pf_be[tid]);
        }
    }
    for (int e=tid;e<CC*CC;e+=blockDim.x){
        int m=e>>6, j=e&63; float s=0.f;
        for (int l=0;l<CC;l++) s += ac_w[m*CC+l]*cf_w2[l*CC+j];
        sT[e]=s;
    }
    __syncthreads();
    for (int e=tid;e<CC*CC;e+=blockDim.x){
        int c=e>>6, j=e&63; float s=0.f;
        for (int m=0;m<CC;m++) s += ge_w1[c*CC+m]*sT[m*CC+j];
        g_WcT[j*CC+c]=s;
    }
    __syncthreads();
    for (int e=tid;e<CC*CC;e+=blockDim.x){
        int m=e>>6, j=e&63; float s=0.f;
        for (int l=0;l<CC;l++) s += ap_w[m*CC+l]*pf_w2[l*CC+j];
        sT[e]=s;
    }
    __syncthreads();
    for (int e=tid;e<CC*CC;e+=blockDim.x){
        int c=e>>6, j=e&63; float s=0.f;
        for (int m=0;m<CC;m++) s += ge_w1[c*CC+m]*sT[m*CC+j];
        g_WpT[j*CC+c]=gam*s;
    }
    if (tid < CC){
        float s1 = ac_b[tid] + gam*ap_b[tid];
        for (int j=0;j<CC;j++) s1 += ac_w[tid*CC+j]*cf_b2[j];
        sv1[tid]=s1;
        float s2 = 0.f;
        for (int j=0;j<CC;j++) s2 += ap_w[tid*CC+j]*pf_b2[j];
        sv2[tid]=s2;
    }
    __syncthreads();
    if (tid < CC){
        float bz = ge_b1[tid], bp = 0.f;
        for (int m=0;m<CC;m++){ bz += ge_w1[tid*CC+m]*sv1[m]; bp += ge_w1[tid*CC+m]*sv2[m]; }
        g_bz[tid]=bz; g_bp[tid]=gam*bp;
    }
    for (int e=tid;e<CC*CC;e+=blockDim.x) g_W2T[(e&63)*CC + (e>>6)] = ge_w2[e];
}

// 128 threads, 2 points/thread (p and p+128)
__global__ __launch_bounds__(128,2) void main_kernel(const float* __restrict__ nxyz,
                                                     const float* __restrict__ cxyz){
    __shared__ float sWcT[CC*CC];
    __shared__ float sWpT[CC*CC];
    __shared__ float sWcf[4*CC], sWpf[5*CC];
    __shared__ float sbcf[CC], sbpf[CC], sbz[CC], sbp[CC];
    __shared__ double sS1[CC], sS2[CC];
    int tid = threadIdx.x;
    for (int i=tid;i<CC*CC;i+=128){ sWcT[i]=g_WcT[i]; sWpT[i]=g_WpT[i]; }
    for (int i=tid;i<4*CC;i+=128) sWcf[i]=g_WcfT[i];
    for (int i=tid;i<5*CC;i+=128) sWpf[i]=g_WpfT[i];
    if (tid < CC){
        sbcf[tid]=g_bcf[tid]; sbpf[tid]=g_bpf[tid];
        sbz[tid]=g_bz[tid];   sbp[tid]=g_bp[tid];
        sS1[tid]=0.0; sS2[tid]=0.0;
    }
    __syncthreads();

    int p0 = blockIdx.x*256 + tid;
    int p1 = p0 + 128;
    Geo ga = geom(nxyz, cxyz, p0);
    Geo gb = geom(nxyz, cxyz, p1);
    Mix mxa = make_mix(ga);
    Mix mxb = make_mix(gb);

    float4 A[16], B[16];
#pragma unroll
    for (int c4=0;c4<16;c4++){ A[c4]=make_float4(0.f,0.f,0.f,0.f); B[c4]=A[c4]; }

    // ---- polar GEMV (shuffle-free) ----
#pragma unroll 2
    for (int j=0;j<CC;j++){
        float hja = sbpf[j], hjb = sbpf[j];
        float w0=sWpf[j], w1=sWpf[CC+j], w2=sWpf[2*CC+j], w3=sWpf[3*CC+j], w4=sWpf[4*CC+j];
        hja = fmaf(ga.rn,w0,hja); hjb = fmaf(gb.rn,w0,hjb);
        hja = fmaf(ga.sth,w1,hja); hjb = fmaf(gb.sth,w1,hjb);
        hja = fmaf(ga.cth,w2,hja); hjb = fmaf(gb.cth,w2,hjb);
        hja = fmaf(ga.sph,w3,hja); hjb = fmaf(gb.sph,w3,hjb);
        hja = fmaf(ga.cph,w4,hja); hjb = fmaf(gb.cph,w4,hjb);
        hja = fmaxf(hja,0.f); hjb = fmaxf(hjb,0.f);
        const float4* wr = (const float4*)(sWpT + j*CC);
#pragma unroll
        for (int c4=0;c4<16;c4++){
            float4 w = wr[c4];
            A[c4].x = fmaf(w.x,hja,A[c4].x); B[c4].x = fmaf(w.x,hjb,B[c4].x);
            A[c4].y = fmaf(w.y,hja,A[c4].y); B[c4].y = fmaf(w.y,hjb,B[c4].y);
            A[c4].z = fmaf(w.z,hja,A[c4].z); B[c4].z = fmaf(w.z,hjb,B[c4].z);
            A[c4].w = fmaf(w.w,hja,A[c4].w); B[c4].w = fmaf(w.w,hjb,B[c4].w);
        }
    }
    // ---- k-mix applied once to accumulated polar part ----
#pragma unroll
    for (int c4=0;c4<16;c4++){
        A[c4].x = mix16(A[c4].x, mxa);  B[c4].x = mix16(B[c4].x, mxb);
        A[c4].y = mix16(A[c4].y, mxa);  B[c4].y = mix16(B[c4].y, mxb);
        A[c4].z = mix16(A[c4].z, mxa);  B[c4].z = mix16(B[c4].z, mxb);
        A[c4].w = mix16(A[c4].w, mxa);  B[c4].w = mix16(B[c4].w, mxb);
    }
    // ---- biases ----
#pragma unroll
    for (int c4=0;c4<16;c4++){
        float4 bz4 = ((const float4*)sbz)[c4];
        float4 bp4 = ((const float4*)sbp)[c4];
        A[c4].x += fmaf(bp4.x, mxa.s_k, bz4.x);  B[c4].x += fmaf(bp4.x, mxb.s_k, bz4.x);
        A[c4].y += fmaf(bp4.y, mxa.s_k, bz4.y);  B[c4].y += fmaf(bp4.y, mxb.s_k, bz4.y);
        A[c4].z += fmaf(bp4.z, mxa.s_k, bz4.z);  B[c4].z += fmaf(bp4.z, mxb.s_k, bz4.z);
        A[c4].w += fmaf(bp4.w, mxa.s_k, bz4.w);  B[c4].w += fmaf(bp4.w, mxb.s_k, bz4.w);
    }
    // ---- cart GEMV ----
#pragma unroll 2
    for (int j=0;j<CC;j++){
        float hja = sbcf[j], hjb = sbcf[j];
        float w0=sWcf[j], w1=sWcf[CC+j], w2=sWcf[2*CC+j], w3=sWcf[3*CC+j];
        hja = fmaf(ga.dx,w0,hja); hjb = fmaf(gb.dx,w0,hjb);
        hja = fmaf(ga.dy,w1,hja); hjb = fmaf(gb.dy,w1,hjb);
        hja = fmaf(ga.dz,w2,hja); hjb = fmaf(gb.dz,w2,hjb);
        hja = fmaf(ga.r ,w3,hja); hjb = fmaf(gb.r ,w3,hjb);
        hja = fmaxf(hja,0.f); hjb = fmaxf(hjb,0.f);
        const float4* wr = (const float4*)(sWcT + j*CC);
#pragma unroll
        for (int c4=0;c4<16;c4++){
            float4 w = wr[c4];
            A[c4].x = fmaf(w.x,hja,A[c4].x); B[c4].x = fmaf(w.x,hjb,B[c4].x);
            A[c4].y = fmaf(w.y,hja,A[c4].y); B[c4].y = fmaf(w.y,hjb,B[c4].y);
            A[c4].z = fmaf(w.z,hja,A[c4].z); B[c4].z = fmaf(w.z,hjb,B[c4].z);
            A[c4].w = fmaf(w.w,hja,A[c4].w); B[c4].w = fmaf(w.w,hjb,B[c4].w);
        }
    }
#pragma unroll
    for (int c4=0;c4<16;c4++){
        g_z1[c4*NPTS + p0] = A[c4];
        g_z1[c4*NPTS + p1] = B[c4];
    }
    // ---- BN3 moments (sum both points before warp-reduce) ----
#pragma unroll
    for (int c4=0;c4<16;c4++){
        float va[4] = {A[c4].x, A[c4].y, A[c4].z, A[c4].w};
        float vb[4] = {B[c4].x, B[c4].y, B[c4].z, B[c4].w};
#pragma unroll
        for (int q=0;q<4;q++){
            float s1 = wsum32(va[q] + vb[q]);
            float s2 = wsum32(va[q]*va[q] + vb[q]*vb[q]);
            if ((tid&31)==0){ atomicAdd(&sS1[4*c4+q],(double)s1); atomicAdd(&sS2[4*c4+q],(double)s2); }
        }
    }
    __syncthreads();
    if (tid < CC){ atomicAdd(&g_zs1[tid], sS1[tid]); atomicAdd(&g_zs2[tid], sS2[tid]); }
}

__global__ void bnstats_kernel(const float* __restrict__ ge_g, const float* __restrict__ ge_be){
    int c = threadIdx.x;
    if (c < CC){
        double mean = g_zs1[c]/(double)NPTS;
        double var  = g_zs2[c]/(double)NPTS - mean*mean;
        double a = (double)ge_g[c]/sqrt(var + 1e-5);
        g_alpha[c] = (float)a;
        g_beta[c]  = (float)((double)ge_be[c] - mean*a);
    }
}

// 128 threads, 2 points/thread
__global__ __launch_bounds__(128,2) void final_kernel(const float* __restrict__ ge_b2,
                                                      float* __restrict__ out){
    __shared__ float sW[CC*CC];
    __shared__ float sa[CC], sbv[CC], sb2[CC];
    int tid = threadIdx.x;
    for (int i=tid;i<CC*CC;i+=128) sW[i]=g_W2T[i];
    if (tid < CC){ sa[tid]=g_alpha[tid]; sbv[tid]=g_beta[tid]; sb2[tid]=ge_b2[tid]; }
    __syncthreads();

    int p0 = blockIdx.x*256 + tid;
    int p1 = p0 + 128;
    float4 A[16], B[16];
#pragma unroll
    for (int c4=0;c4<16;c4++){
        float4 b4 = ((const float4*)sb2)[c4];
        A[c4]=b4; B[c4]=b4;
    }
#pragma unroll 2
    for (int j4=0;j4<16;j4++){
        float4 za = g_z1[j4*NPTS + p0];
        float4 zb = g_z1[j4*NPTS + p1];
        float4 a4 = ((const float4*)sa)[j4];
        float4 bb4 = ((const float4*)sbv)[j4];
        float ha[4], hb[4];
        ha[0]=fmaxf(fmaf(za.x,a4.x,bb4.x),0.f); hb[0]=fmaxf(fmaf(zb.x,a4.x,bb4.x),0.f);
        ha[1]=fmaxf(fmaf(za.y,a4.y,bb4.y),0.f); hb[1]=fmaxf(fmaf(zb.y,a4.y,bb4.y),0.f);
        ha[2]=fmaxf(fmaf(za.z,a4.z,bb4.z),0.f); hb[2]=fmaxf(fmaf(zb.z,a4.z,bb4.z),0.f);
        ha[3]=fmaxf(fmaf(za.w,a4.w,bb4.w),0.f); hb[3]=fmaxf(fmaf(zb.w,a4.w,bb4.w),0.f);
#pragma unroll
        for (int q=0;q<4;q++){
            int j = j4*4 + q;
            const float4* wr = (const float4*)(sW + j*CC);
            float hja = ha[q], hjb = hb[q];
#pragma unroll
            for (int c4=0;c4<16;c4++){
                float4 w = wr[c4];
                A[c4].x = fmaf(w.x,hja,A[c4].x); B[c4].x = fmaf(w.x,hjb,B[c4].x);
                A[c4].y = fmaf(w.y,hja,A[c4].y); B[c4].y = fmaf(w.y,hjb,B[c4].y);
                A[c4].z = fmaf(w.z,hja,A[c4].z); B[c4].z = fmaf(w.z,hjb,B[c4].z);
                A[c4].w = fmaf(w.w,hja,A[c4].w); B[c4].w = fmaf(w.w,hjb,B[c4].w);
            }
        }
    }
    {
        int b = p0>>16, nk = p0 & 65535;
        float* ob = out + (size_t)b*CC*NN*KK + nk;
#pragma unroll
        for (int c4=0;c4<16;c4++){
            ob[(size_t)(4*c4+0)*NN*KK] = A[c4].x;
            ob[(size_t)(4*c4+1)*NN*KK] = A[c4].y;
            ob[(size_t)(4*c4+2)*NN*KK] = A[c4].z;
            ob[(size_t)(4*c4+3)*NN*KK] = A[c4].w;
        }
    }
    {
        int b = p1>>16, nk = p1 & 65535;
        float* ob = out + (size_t)b*CC*NN*KK + nk;
#pragma unroll
        for (int c4=0;c4<16;c4++){
            ob[(size_t)(4*c4+0)*NN*KK] = B[c4].x;
            ob[(size_t)(4*c4+1)*NN*KK] = B[c4].y;
            ob[(size_t)(4*c4+2)*NN*KK] = B[c4].z;
            ob[(size_t)(4*c4+3)*NN*KK] = B[c4].w;
        }
    }
}

extern "C" void kernel_launch(void* const* d_in, const int* in_sizes, int n_in,
                              void* d_out, int out_size){
    const float* nxyz  = (const float*)d_in[0];
    const float* cxyz  = (const float*)d_in[1];
    const float* cf_w1 = (const float*)d_in[2];
    const float* cf_b1 = (const float*)d_in[3];
    const float* cf_g  = (const float*)d_in[4];
    const float* cf_be = (const float*)d_in[5];
    const float* cf_w2 = (const float*)d_in[6];
    const float* cf_b2 = (const float*)d_in[7];
    const float* pf_w1 = (const float*)d_in[8];
    const float* pf_b1 = (const float*)d_in[9];
    const float* pf_g  = (const float*)d_in[10];
    const float* pf_be = (const float*)d_in[11];
    const float* pf_w2 = (const float*)d_in[12];
    const float* pf_b2 = (const float*)d_in[13];
    const float* ac_w  = (const float*)d_in[14];
    const float* ac_b  = (const float*)d_in[15];
    const float* ap_w  = (const float*)d_in[16];
    const float* ap_b  = (const float*)d_in[17];
    const float* gamma = (const float*)d_in[18];
    const float* ge_w1 = (const float*)d_in[19];
    const float* ge_b1 = (const float*)d_in[20];
    const float* ge_g  = (const float*)d_in[21];
    const float* ge_be = (const float*)d_in[22];
    const float* ge_w2 = (const float*)d_in[23];
    const float* ge_b2 = (const float*)d_in[24];
    float* out = (float*)d_out;

    zero_kernel<<<1, 64>>>();
    moments_kernel<<<NPTS/256, 256>>>(nxyz, cxyz);
    setup_kernel<<<1, 256>>>(cf_w1, cf_b1, cf_g, cf_be, cf_w2, cf_b2,
                             pf_w1, pf_b1, pf_g, pf_be, pf_w2, pf_b2,
                             ac_w, ac_b, ap_w, ap_b, gamma,
                             ge_w1, ge_b1, ge_w2);
    main_kernel<<<NPTS/256, 128>>>(nxyz, cxyz);
    bnstats_kernel<<<1, 64>>>(ge_g, ge_be);
    final_kernel<<<NPTS/256, 128>>>(ge_b2, out);
}

// round 4
// speedup vs baseline: 1.3987x; 1.1359x over previous
#include <cuda_runtime.h>
#include <math.h>

#define BB 8
#define NN 4096
#define KK 16
#define CC 64
#define NPTS (BB*NN*KK)
#define EPSF 1e-6f
#define PI_F 3.14159265358979323846f

__device__ double g_mom[34];
__device__ double g_zs1[CC];
__device__ double g_zs2[CC];
__device__ float  g_WcfT[4*CC];
__device__ float  g_bcf[CC];
__device__ float  g_WpfT[5*CC];
__device__ float  g_bpf[CC];
__device__ float  g_Wmain[128*CC];   // rows 0-63: Wc[j][c]; rows 64-127: gamma*Wp[j][c]
__device__ float  g_bz[CC];
__device__ float  g_bp[CC];
__device__ float  g_W2T[CC*CC];      // [j][c]
__device__ float  g_alpha[CC];
__device__ float  g_beta[CC];
__device__ float  g_z1[CC*NPTS];     // [c][p], 134 MB

__device__ __forceinline__ float wsum32(float v){
#pragma unroll
    for (int m=1; m<32; m<<=1) v += __shfl_xor_sync(0xffffffffu, v, m);
    return v;
}
__device__ __forceinline__ float gsum16(float v){
#pragma unroll
    for (int m=1; m<16; m<<=1) v += __shfl_xor_sync(0xffffffffu, v, m);
    return v;
}
__device__ __forceinline__ int clampi(int x,int lo,int hi){return x<lo?lo:(x>hi?hi:x);}

struct Geo { float dx,dy,dz,r,rn,sth,cth,sph,cph,theta; };

__device__ __forceinline__ Geo geom(const float* __restrict__ nxyz,
                                    const float* __restrict__ cxyz, int p){
    int b = p>>16, n = (p>>4)&(NN-1), k = p&(KK-1);
    int cb = (b*3)*NN + n;
    float cx=cxyz[cb], cy=cxyz[cb+NN], cz=cxyz[cb+2*NN];
    int nb = ((b*3)*NN + n)*KK + k;
    Geo g;
    g.dx = nxyz[nb]           - cx;
    g.dy = nxyz[nb+NN*KK]     - cy;
    g.dz = nxyz[nb+2*NN*KK]   - cz;
    float r = sqrtf(g.dx*g.dx + g.dy*g.dy + g.dz*g.dz); r = fmaxf(r, EPSF);
    float rho = fmaxf(sqrtf(g.dx*g.dx + g.dy*g.dy), EPSF);
    g.r = r;
    g.theta = atan2f(g.dy, g.dx);
    float phi = atan2f(g.dz, rho);
    float rmean = gsum16(r) * (1.0f/16.0f);
    g.rn = fminf(r/(rmean+EPSF), 3.0f) * (1.0f/3.0f);
    sincosf(g.theta, &g.sth, &g.cth);
    sincosf(phi, &g.sph, &g.cph);
    return g;
}

struct Mix { float c0,c1,c2,c3, m0,m1,m2,m3, s_k; };

__device__ __forceinline__ Mix make_mix(const Geo& g){
    float ridx = g.rn*(2.0f - 1e-6f);
    float aidx = ((g.theta + PI_F)*(0.5f/PI_F))*(12.0f - 1e-6f);
    float ri0f = floorf(ridx); float rw1 = ridx-ri0f, rw0 = 1.0f-rw1;
    int ri0 = clampi((int)ri0f,0,1), ri1 = clampi((int)ri0f+1,0,1);
    float ai0f = floorf(aidx); float aw1 = aidx-ai0f, aw0 = 1.0f-aw1;
    int ai0 = clampi((int)ai0f,0,11), ai1 = clampi((int)ai0f+1,0,11);
    float w00=rw0*aw0, w01=rw0*aw1, w10=rw1*aw0, w11=rw1*aw1;
    int c00=ri0*12+ai0, c01=ri0*12+ai1, c10=ri1*12+ai0, c11=ri1*12+ai1;

    int t0 = __shfl_sync(0xffffffffu, c00, 0, 16);
    int t1 = __shfl_sync(0xffffffffu, c01, 0, 16);
    int t2 = __shfl_sync(0xffffffffu, c10, 0, 16);
    int t3 = __shfl_sync(0xffffffffu, c11, 0, 16);

    Mix mx;
    mx.c0 = (c00==t0?w00:0.f)+(c01==t0?w01:0.f)+(c10==t0?w10:0.f)+(c11==t0?w11:0.f);
    mx.c1 = (c00==t1?w00:0.f)+(c01==t1?w01:0.f)+(c10==t1?w10:0.f)+(c11==t1?w11:0.f);
    mx.c2 = (c00==t2?w00:0.f)+(c01==t2?w01:0.f)+(c10==t2?w10:0.f)+(c11==t2?w11:0.f);
    mx.c3 = (c00==t3?w00:0.f)+(c01==t3?w01:0.f)+(c10==t3?w10:0.f)+(c11==t3?w11:0.f);

    float den0 = gsum16(mx.c0), den1 = gsum16(mx.c1);
    float den2 = gsum16(mx.c2), den3 = gsum16(mx.c3);
    mx.m0 = w00/fmaxf(den0,EPSF); mx.m1 = w01/fmaxf(den1,EPSF);
    mx.m2 = w10/fmaxf(den2,EPSF); mx.m3 = w11/fmaxf(den3,EPSF);
    mx.s_k = mx.m0*den0 + mx.m1*den1 + mx.m2*den2 + mx.m3*den3;
    return mx;
}

__global__ void zero_kernel(){
    int t = threadIdx.x;
    if (t < 34) g_mom[t] = 0.0;
    if (t < CC) { g_zs1[t]=0.0; g_zs2[t]=0.0; }
}

__global__ __launch_bounds__(256) void moments_kernel(const float* __restrict__ nxyz,
                                                      const float* __restrict__ cxyz){
    __shared__ double smom[34];
    int tid = threadIdx.x;
    if (tid < 34) smom[tid] = 0.0;
    __syncthreads();
    int p = blockIdx.x*256 + tid;
    Geo g = geom(nxyz, cxyz, p);
    float fc[4] = {g.dx, g.dy, g.dz, g.r};
    float fp[5] = {g.rn, g.sth, g.cth, g.sph, g.cph};
    float v[34];
#pragma unroll
    for (int i=0;i<4;i++){
        v[i] = fc[i];
#pragma unroll
        for (int j=i;j<4;j++) v[4 + i*4 - (i*(i-1))/2 + (j-i)] = fc[i]*fc[j];
    }
#pragma unroll
    for (int i=0;i<5;i++){
        v[14+i] = fp[i];
#pragma unroll
        for (int j=i;j<5;j++) v[19 + i*5 - (i*(i-1))/2 + (j-i)] = fp[i]*fp[j];
    }
#pragma unroll
    for (int i=0;i<34;i++){
        float s = wsum32(v[i]);
        if ((tid&31)==0) atomicAdd(&smom[i], (double)s);
    }
    __syncthreads();
    if (tid < 34) atomicAdd(&g_mom[tid], smom[tid]);
}

__global__ void setup_kernel(
    const float* __restrict__ cf_w1, const float* __restrict__ cf_b1,
    const float* __restrict__ cf_g,  const float* __restrict__ cf_be,
    const float* __restrict__ cf_w2, const float* __restrict__ cf_b2,
    const float* __restrict__ pf_w1, const float* __restrict__ pf_b1,
    const float* __restrict__ pf_g,  const float* __restrict__ pf_be,
    const float* __restrict__ pf_w2, const float* __restrict__ pf_b2,
    const float* __restrict__ ac_w,  const float* __restrict__ ac_b,
    const float* __restrict__ ap_w,  const float* __restrict__ ap_b,
    const float* __restrict__ gamma_p,
    const float* __restrict__ ge_w1, const float* __restrict__ ge_b1,
    const float* __restrict__ ge_w2)
{
    __shared__ float sT[CC*CC];
    __shared__ float sv1[CC], sv2[CC];
    int tid = threadIdx.x;
    float gam = gamma_p[0];
    const double inv = 1.0/(double)NPTS;

    if (tid < CC){
        { // cart BN fold
            double mu[4], cov[4][4];
#pragma unroll
            for (int i=0;i<4;i++) mu[i] = g_mom[i]*inv;
#pragma unroll
            for (int i=0;i<4;i++)
#pragma unroll
                for (int j=i;j<4;j++){
                    double c2 = g_mom[4 + i*4 - (i*(i-1))/2 + (j-i)]*inv - mu[i]*mu[j];
                    cov[i][j]=c2; cov[j][i]=c2;
                }
            double w[4], m=(double)cf_b1[tid], vv=0.0;
#pragma unroll
            for (int i=0;i<4;i++){ w[i]=(double)cf_w1[tid*4+i]; m += w[i]*mu[i]; }
#pragma unroll
            for (int i=0;i<4;i++)
#pragma unroll
                for (int j=0;j<4;j++) vv += w[i]*w[j]*cov[i][j];
            double al = (double)cf_g[tid]/sqrt(vv+1e-5);
#pragma unroll
            for (int i=0;i<4;i++) g_WcfT[i*CC+tid] = (float)(w[i]*al);
            g_bcf[tid] = (float)(((double)cf_b1[tid]-m)*al + (double)cf_be[tid]);
        }
        { // polar BN fold
            double mu[5], cov[5][5];
#pragma unroll
            for (int i=0;i<5;i++) mu[i] = g_mom[14+i]*inv;
#pragma unroll
            for (int i=0;i<5;i++)
#pragma unroll
                for (int j=i;j<5;j++){
                    double c2 = g_mom[19 + i*5 - (i*(i-1))/2 + (j-i)]*inv - mu[i]*mu[j];
                    cov[i][j]=c2; cov[j][i]=c2;
                }
            double w[5], m=(double)pf_b1[tid], vv=0.0;
#pragma unroll
            for (int i=0;i<5;i++){ w[i]=(double)pf_w1[tid*5+i]; m += w[i]*mu[i]; }
#pragma unroll
            for (int i=0;i<5;i++)
#pragma unroll
                for (int j=0;j<5;j++) vv += w[i]*w[j]*cov[i][j];
            double al = (double)pf_g[tid]/sqrt(vv+1e-5);
#pragma unroll
            for (int i=0;i<5;i++) g_WpfT[i*CC+tid] = (float)(w[i]*al);
            g_bpf[tid] = (float)(((double)pf_b1[tid]-m)*al + (double)pf_be[tid]);
        }
    }
    // T1 = ac_w @ cf_w2 ; Wmain[j][c] (rows 0-63) = (ge_w1 @ T1)[c][j]
    for (int e=tid;e<CC*CC;e+=blockDim.x){
        int m=e>>6, j=e&63; float s=0.f;
        for (int l=0;l<CC;l++) s += ac_w[m*CC+l]*cf_w2[l*CC+j];
        sT[e]=s;
    }
    __syncthreads();
    for (int e=tid;e<CC*CC;e+=blockDim.x){
        int c=e>>6, j=e&63; float s=0.f;
        for (int m=0;m<CC;m++) s += ge_w1[c*CC+m]*sT[m*CC+j];
        g_Wmain[j*CC+c]=s;
    }
    __syncthreads();
    // T2 = ap_w @ pf_w2 ; Wmain rows 64-127 = gamma * (ge_w1 @ T2)^T
    for (int e=tid;e<CC*CC;e+=blockDim.x){
        int m=e>>6, j=e&63; float s=0.f;
        for (int l=0;l<CC;l++) s += ap_w[m*CC+l]*pf_w2[l*CC+j];
        sT[e]=s;
    }
    __syncthreads();
    for (int e=tid;e<CC*CC;e+=blockDim.x){
        int c=e>>6, j=e&63; float s=0.f;
        for (int m=0;m<CC;m++) s += ge_w1[c*CC+m]*sT[m*CC+j];
        g_Wmain[(64+j)*CC+c]=gam*s;
    }
    if (tid < CC){
        float s1 = ac_b[tid] + gam*ap_b[tid];
        for (int j=0;j<CC;j++) s1 += ac_w[tid*CC+j]*cf_b2[j];
        sv1[tid]=s1;
        float s2 = 0.f;
        for (int j=0;j<CC;j++) s2 += ap_w[tid*CC+j]*pf_b2[j];
        sv2[tid]=s2;
    }
    __syncthreads();
    if (tid < CC){
        float bz = ge_b1[tid], bp = 0.f;
        for (int m=0;m<CC;m++){ bz += ge_w1[tid*CC+m]*sv1[m]; bp += ge_w1[tid*CC+m]*sv2[m]; }
        g_bz[tid]=bz; g_bp[tid]=gam*bp;
    }
    for (int e=tid;e<CC*CC;e+=blockDim.x) g_W2T[(e&63)*CC + (e>>6)] = ge_w2[e];
}

// smem float offsets for main_kernel
#define MO_W    0        // 128*64 = 8192
#define MO_HC   8192     // 64*128
#define MO_HP   16384    // 64*128
#define MO_C    24576    // 4*128
#define MO_M    25088    // 4*128
#define MO_SK   25600    // 128
#define MO_BZ   25728    // 64
#define MO_BP   25792    // 64
#define MO_WCF  25856    // 256
#define MO_BCF  26112    // 64
#define MO_WPF  26176    // 320
#define MO_BPF  26496    // 64
#define MAIN_SMEM_FLOATS 26560

__global__ __launch_bounds__(128,2) void main_kernel(const float* __restrict__ nxyz,
                                                     const float* __restrict__ cxyz){
    extern __shared__ float sm[];
    float* sW   = sm + MO_W;
    float* sHC  = sm + MO_HC;
    float* sHP  = sm + MO_HP;
    float* sCc  = sm + MO_C;
    float* sMm  = sm + MO_M;
    float* sSK  = sm + MO_SK;
    float* sbz  = sm + MO_BZ;
    float* sbp  = sm + MO_BP;
    float* sWcf = sm + MO_WCF;
    float* sbcf = sm + MO_BCF;
    float* sWpf = sm + MO_WPF;
    float* sbpf = sm + MO_BPF;
    int tid = threadIdx.x;

    // phase 0: load weights
    for (int i=tid;i<128*CC;i+=128) sW[i]=g_Wmain[i];
    for (int i=tid;i<4*CC;i+=128) sWcf[i]=g_WcfT[i];
    for (int i=tid;i<5*CC;i+=128) sWpf[i]=g_WpfT[i];
    if (tid < CC){
        sbcf[tid]=g_bcf[tid]; sbpf[tid]=g_bpf[tid];
        sbz[tid]=g_bz[tid];   sbp[tid]=g_bp[tid];
    }
    __syncthreads();

    // phase 1: per-thread point -> geometry, mix coefs, Hc/Hp columns
    int p0 = blockIdx.x*128;
    {
        int p = p0 + tid;
        Geo g = geom(nxyz, cxyz, p);
        Mix mx = make_mix(g);
        sCc[0*128+tid]=mx.c0; sCc[1*128+tid]=mx.c1; sCc[2*128+tid]=mx.c2; sCc[3*128+tid]=mx.c3;
        sMm[0*128+tid]=mx.m0; sMm[1*128+tid]=mx.m1; sMm[2*128+tid]=mx.m2; sMm[3*128+tid]=mx.m3;
        sSK[tid]=mx.s_k;
#pragma unroll 4
        for (int j=0;j<CC;j++){
            float hc = sbcf[j];
            hc = fmaf(g.dx, sWcf[j],       hc);
            hc = fmaf(g.dy, sWcf[64+j],    hc);
            hc = fmaf(g.dz, sWcf[128+j],   hc);
            hc = fmaf(g.r,  sWcf[192+j],   hc);
            sHC[j*128+tid] = fmaxf(hc, 0.f);
            float hp = sbpf[j];
            hp = fmaf(g.rn,  sWpf[j],      hp);
            hp = fmaf(g.sth, sWpf[64+j],   hp);
            hp = fmaf(g.cth, sWpf[128+j],  hp);
            hp = fmaf(g.sph, sWpf[192+j],  hp);
            hp = fmaf(g.cph, sWpf[256+j],  hp);
            sHP[j*128+tid] = fmaxf(hp, 0.f);
        }
    }
    __syncthreads();

    // phase 1.5: k-mix applied to Hp in smem. 512 tasks = 64 rows x 8 groups.
#pragma unroll
    for (int t4=0;t4<4;t4++){
        int tk = t4*128 + tid;
        int j = tk>>3, grp = tk&7;
        float* hrow = sHP + j*128 + grp*16;
        const float* cb = sCc + grp*16;
        const float* mb = sMm + grp*16;
        float h[16];
#pragma unroll
        for (int k=0;k<16;k++) h[k]=hrow[k];
        float g0=0.f,g1=0.f,g2=0.f,g3=0.f;
#pragma unroll
        for (int k=0;k<16;k++){
            g0 = fmaf(cb[0*128+k], h[k], g0);
            g1 = fmaf(cb[1*128+k], h[k], g1);
            g2 = fmaf(cb[2*128+k], h[k], g2);
            g3 = fmaf(cb[3*128+k], h[k], g3);
        }
#pragma unroll
        for (int k=0;k<16;k++){
            float o = mb[0*128+k]*g0;
            o = fmaf(mb[1*128+k], g1, o);
            o = fmaf(mb[2*128+k], g2, o);
            o = fmaf(mb[3*128+k], g3, o);
            hrow[k] = o;
        }
    }
    __syncthreads();

    // phase 2: GEMM  Z[64][128] = W[128x64]^T-applied . [Hc; Hp']
    int cm = tid>>4, qn = tid&15;
    int c0 = cm*8, q0 = qn*8;
    float acc[64];
#pragma unroll
    for (int i=0;i<8;i++){
        float bzv = sbz[c0+i], bpv = sbp[c0+i];
#pragma unroll
        for (int q=0;q<8;q++) acc[i*8+q] = fmaf(bpv, sSK[q0+q], bzv);
    }
#pragma unroll 1
    for (int half=0; half<2; half++){
        const float* Wb = sW + half*64*CC;
        const float* Hb = half ? sHP : sHC;
#pragma unroll 4
        for (int k=0;k<64;k++){
            float4 w0 = *(const float4*)(Wb + k*CC + c0);
            float4 w1 = *(const float4*)(Wb + k*CC + c0 + 4);
            float4 h0 = *(const float4*)(Hb + k*128 + q0);
            float4 h1 = *(const float4*)(Hb + k*128 + q0 + 4);
            float wv[8] = {w0.x,w0.y,w0.z,w0.w,w1.x,w1.y,w1.z,w1.w};
            float hv[8] = {h0.x,h0.y,h0.z,h0.w,h1.x,h1.y,h1.z,h1.w};
#pragma unroll
            for (int i=0;i<8;i++)
#pragma unroll
                for (int q=0;q<8;q++) acc[i*8+q] = fmaf(wv[i], hv[q], acc[i*8+q]);
        }
    }
    // store z1
    size_t pbase = (size_t)p0 + q0;
#pragma unroll
    for (int i=0;i<8;i++){
        float* row = g_z1 + (size_t)(c0+i)*NPTS + pbase;
        *(float4*)row     = make_float4(acc[i*8+0],acc[i*8+1],acc[i*8+2],acc[i*8+3]);
        *(float4*)(row+4) = make_float4(acc[i*8+4],acc[i*8+5],acc[i*8+6],acc[i*8+7]);
    }
    // BN3 moments: reduce across the 16 lanes sharing cm
    float s1v[8], s2v[8];
#pragma unroll
    for (int i=0;i<8;i++){
        float s1=0.f, s2=0.f;
#pragma unroll
        for (int q=0;q<8;q++){ float v=acc[i*8+q]; s1+=v; s2=fmaf(v,v,s2); }
        s1v[i]=gsum16(s1); s2v[i]=gsum16(s2);
    }
    if (qn==0){
#pragma unroll
        for (int i=0;i<8;i++){
            atomicAdd(&g_zs1[c0+i], (double)s1v[i]);
            atomicAdd(&g_zs2[c0+i], (double)s2v[i]);
        }
    }
}

__global__ void bnstats_kernel(const float* __restrict__ ge_g, const float* __restrict__ ge_be){
    int c = threadIdx.x;
    if (c < CC){
        double mean = g_zs1[c]/(double)NPTS;
        double var  = g_zs2[c]/(double)NPTS - mean*mean;
        double a = (double)ge_g[c]/sqrt(var + 1e-5);
        g_alpha[c] = (float)a;
        g_beta[c]  = (float)((double)ge_be[c] - mean*a);
    }
}

// final kernel smem offsets
#define FO_W    0        // 64*64 = 4096
#define FO_H    4096     // 64*128 = 8192
#define FO_A    12288    // 64
#define FO_B    12352    // 64
#define FO_B2   12416    // 64
#define FINAL_SMEM_FLOATS 12480

__global__ __launch_bounds__(128,3) void final_kernel(const float* __restrict__ ge_b2,
                                                      float* __restrict__ out){
    extern __shared__ float sm[];
    float* sW  = sm + FO_W;
    float* sH  = sm + FO_H;
    float* sa  = sm + FO_A;
    float* sbv = sm + FO_B;
    float* sb2 = sm + FO_B2;
    int tid = threadIdx.x;
    for (int i=tid;i<CC*CC;i+=128) sW[i]=g_W2T[i];
    if (tid < CC){ sa[tid]=g_alpha[tid]; sbv[tid]=g_beta[tid]; sb2[tid]=ge_b2[tid]; }
    __syncthreads();

    int p0 = blockIdx.x*128;
    // phase 1: load z column, affine+relu -> smem
#pragma unroll 4
    for (int k=0;k<CC;k++){
        float z = g_z1[(size_t)k*NPTS + p0 + tid];
        sH[k*128+tid] = fmaxf(fmaf(z, sa[k], sbv[k]), 0.f);
    }
    __syncthreads();

    int cm = tid>>4, qn = tid&15;
    int c0 = cm*8, q0 = qn*8;
    float acc[64];
#pragma unroll
    for (int i=0;i<8;i++){
        float b = sb2[c0+i];
#pragma unroll
        for (int q=0;q<8;q++) acc[i*8+q] = b;
    }
#pragma unroll 4
    for (int k=0;k<CC;k++){
        float4 w0 = *(const float4*)(sW + k*CC + c0);
        float4 w1 = *(const float4*)(sW + k*CC + c0 + 4);
        float4 h0 = *(const float4*)(sH + k*128 + q0);
        float4 h1 = *(const float4*)(sH + k*128 + q0 + 4);
        float wv[8] = {w0.x,w0.y,w0.z,w0.w,w1.x,w1.y,w1.z,w1.w};
        float hv[8] = {h0.x,h0.y,h0.z,h0.w,h1.x,h1.y,h1.z,h1.w};
#pragma unroll
        for (int i=0;i<8;i++)
#pragma unroll
            for (int q=0;q<8;q++) acc[i*8+q] = fmaf(wv[i], hv[q], acc[i*8+q]);
    }
    int b = p0>>16;
    int nk0 = (p0 & 65535) + q0;
#pragma unroll
    for (int i=0;i<8;i++){
        float* row = out + (size_t)b*CC*65536 + (size_t)(c0+i)*65536 + nk0;
        *(float4*)row     = make_float4(acc[i*8+0],acc[i*8+1],acc[i*8+2],acc[i*8+3]);
        *(float4*)(row+4) = make_float4(acc[i*8+4],acc[i*8+5],acc[i*8+6],acc[i*8+7]);
    }
}

extern "C" void kernel_launch(void* const* d_in, const int* in_sizes, int n_in,
                              void* d_out, int out_size){
    const float* nxyz  = (const float*)d_in[0];
    const float* cxyz  = (const float*)d_in[1];
    const float* cf_w1 = (const float*)d_in[2];
    const float* cf_b1 = (const float*)d_in[3];
    const float* cf_g  = (const float*)d_in[4];
    const float* cf_be = (const float*)d_in[5];
    const float* cf_w2 = (const float*)d_in[6];
    const float* cf_b2 = (const float*)d_in[7];
    const float* pf_w1 = (const float*)d_in[8];
    const float* pf_b1 = (const float*)d_in[9];
    const float* pf_g  = (const float*)d_in[10];
    const float* pf_be = (const float*)d_in[11];
    const float* pf_w2 = (const float*)d_in[12];
    const float* pf_b2 = (const float*)d_in[13];
    const float* ac_w  = (const float*)d_in[14];
    const float* ac_b  = (const float*)d_in[15];
    const float* ap_w  = (const float*)d_in[16];
    const float* ap_b  = (const float*)d_in[17];
    const float* gamma = (const float*)d_in[18];
    const float* ge_w1 = (const float*)d_in[19];
    const float* ge_b1 = (const float*)d_in[20];
    const float* ge_g  = (const float*)d_in[21];
    const float* ge_be = (const float*)d_in[22];
    const float* ge_w2 = (const float*)d_in[23];
    const float* ge_b2 = (const float*)d_in[24];
    float* out = (float*)d_out;

    static int attr_done = 0;
    if (!attr_done){
        cudaFuncSetAttribute(main_kernel, cudaFuncAttributeMaxDynamicSharedMemorySize,
                             MAIN_SMEM_FLOATS*4);
        cudaFuncSetAttribute(final_kernel, cudaFuncAttributeMaxDynamicSharedMemorySize,
                             FINAL_SMEM_FLOATS*4);
        attr_done = 1;
    }

    zero_kernel<<<1, 64>>>();
    moments_kernel<<<NPTS/256, 256>>>(nxyz, cxyz);
    setup_kernel<<<1, 256>>>(cf_w1, cf_b1, cf_g, cf_be, cf_w2, cf_b2,
                             pf_w1, pf_b1, pf_g, pf_be, pf_w2, pf_b2,
                             ac_w, ac_b, ap_w, ap_b, gamma,
                             ge_w1, ge_b1, ge_w2);
    main_kernel<<<NPTS/128, 128, MAIN_SMEM_FLOATS*4>>>(nxyz, cxyz);
    bnstats_kernel<<<1, 64>>>(ge_g, ge_be);
    final_kernel<<<NPTS/128, 128, FINAL_SMEM_FLOATS*4>>>(ge_b2, out);
}

// round 7
// speedup vs baseline: 1.7090x; 1.2218x over previous
#include <cuda_runtime.h>
#include <cuda_bf16.h>
#include <math.h>
#include <stdint.h>

#define BB 8
#define NN 4096
#define KK 16
#define CC 64
#define NPTS (BB*NN*KK)
#define EPSF 1e-6f
#define PI_F 3.14159265358979323846f

// ---------------- device globals ----------------
__device__ double g_mom[34];
__device__ double g_zs1[CC];
__device__ double g_zs2[CC];
__device__ float  g_WcfT[4*CC];
__device__ float  g_bcf[CC];
__device__ float  g_WpfT[5*CC];
__device__ float  g_bpf[CC];
__device__ float  g_Wmain[128*CC];   // [k][c] k=0..63 cart, 64..127 gamma*polar
__device__ float  g_bz[CC];
__device__ float  g_bp[CC];
__device__ float  g_alpha[CC];
__device__ float  g_beta[CC];
__device__ float  g_z1[CC*NPTS];     // [c][p]
// bf16 split weights, fragment-friendly [c][k] row-major
__device__ __nv_bfloat16 g_Whi[CC*128];
__device__ __nv_bfloat16 g_Wlo[CC*128];
__device__ __nv_bfloat16 g_W2hi[CC*CC];
__device__ __nv_bfloat16 g_W2lo[CC*CC];

// ---------------- helpers ----------------
#define MMA_BF16(d0,d1,d2,d3,a0,a1,a2,a3,b0,b1) \
    asm volatile("mma.sync.aligned.m16n8k16.row.col.f32.bf16.bf16.f32 " \
        "{%0,%1,%2,%3}, {%4,%5,%6,%7}, {%8,%9}, {%0,%1,%2,%3};" \
        : "+f"(d0),"+f"(d1),"+f"(d2),"+f"(d3) \
        : "r"(a0),"r"(a1),"r"(a2),"r"(a3),"r"(b0),"r"(b1))

__device__ __forceinline__ void split2(float v0, float v1, uint32_t& hp, uint32_t& lp){
    __nv_bfloat16 h0 = __float2bfloat16_rn(v0);
    __nv_bfloat16 h1 = __float2bfloat16_rn(v1);
    float r0 = v0 - __bfloat162float(h0);
    float r1 = v1 - __bfloat162float(h1);
    __nv_bfloat16 l0 = __float2bfloat16_rn(r0);
    __nv_bfloat16 l1 = __float2bfloat16_rn(r1);
    hp = (uint32_t)(*(uint16_t*)&h0) | ((uint32_t)(*(uint16_t*)&h1) << 16);
    lp = (uint32_t)(*(uint16_t*)&l0) | ((uint32_t)(*(uint16_t*)&l1) << 16);
}

__device__ __forceinline__ float wsum32(float v){
#pragma unroll
    for (int m=1; m<32; m<<=1) v += __shfl_xor_sync(0xffffffffu, v, m);
    return v;
}
__device__ __forceinline__ float gsum16(float v){
#pragma unroll
    for (int m=1; m<16; m<<=1) v += __shfl_xor_sync(0xffffffffu, v, m);
    return v;
}
__device__ __forceinline__ int clampi(int x,int lo,int hi){return x<lo?lo:(x>hi?hi:x);}

struct Geo { float dx,dy,dz,r,rn,sth,cth,sph,cph,theta; };
__device__ __forceinline__ Geo geom(const float* __restrict__ nxyz,
                                    const float* __restrict__ cxyz, int p){
    int b = p>>16, n = (p>>4)&(NN-1), k = p&(KK-1);
    int cb = (b*3)*NN + n;
    float cx=cxyz[cb], cy=cxyz[cb+NN], cz=cxyz[cb+2*NN];
    int nb = ((b*3)*NN + n)*KK + k;
    Geo g;
    g.dx = nxyz[nb]         - cx;
    g.dy = nxyz[nb+NN*KK]   - cy;
    g.dz = nxyz[nb+2*NN*KK] - cz;
    float r = sqrtf(g.dx*g.dx + g.dy*g.dy + g.dz*g.dz); r = fmaxf(r, EPSF);
    float rho = fmaxf(sqrtf(g.dx*g.dx + g.dy*g.dy), EPSF);
    g.r = r;
    g.theta = atan2f(g.dy, g.dx);
    float phi = atan2f(g.dz, rho);
    float rmean = gsum16(r) * (1.0f/16.0f);
    g.rn = fminf(r/(rmean+EPSF), 3.0f) * (1.0f/3.0f);
    sincosf(g.theta, &g.sth, &g.cth);
    sincosf(phi, &g.sph, &g.cph);
    return g;
}
struct Mix { float c0,c1,c2,c3, m0,m1,m2,m3, s_k; };
__device__ __forceinline__ Mix make_mix(const Geo& g){
    float ridx = g.rn*(2.0f - 1e-6f);
    float aidx = ((g.theta + PI_F)*(0.5f/PI_F))*(12.0f - 1e-6f);
    float ri0f = floorf(ridx); float rw1 = ridx-ri0f, rw0 = 1.0f-rw1;
    int ri0 = clampi((int)ri0f,0,1), ri1 = clampi((int)ri0f+1,0,1);
    float ai0f = floorf(aidx); float aw1 = aidx-ai0f, aw0 = 1.0f-aw1;
    int ai0 = clampi((int)ai0f,0,11), ai1 = clampi((int)ai0f+1,0,11);
    float w00=rw0*aw0, w01=rw0*aw1, w10=rw1*aw0, w11=rw1*aw1;
    int c00=ri0*12+ai0, c01=ri0*12+ai1, c10=ri1*12+ai0, c11=ri1*12+ai1;
    int t0 = __shfl_sync(0xffffffffu, c00, 0, 16);
    int t1 = __shfl_sync(0xffffffffu, c01, 0, 16);
    int t2 = __shfl_sync(0xffffffffu, c10, 0, 16);
    int t3 = __shfl_sync(0xffffffffu, c11, 0, 16);
    Mix mx;
    mx.c0 = (c00==t0?w00:0.f)+(c01==t0?w01:0.f)+(c10==t0?w10:0.f)+(c11==t0?w11:0.f);
    mx.c1 = (c00==t1?w00:0.f)+(c01==t1?w01:0.f)+(c10==t1?w10:0.f)+(c11==t1?w11:0.f);
    mx.c2 = (c00==t2?w00:0.f)+(c01==t2?w01:0.f)+(c10==t2?w10:0.f)+(c11==t2?w11:0.f);
    mx.c3 = (c00==t3?w00:0.f)+(c01==t3?w01:0.f)+(c10==t3?w10:0.f)+(c11==t3?w11:0.f);
    float den0 = gsum16(mx.c0), den1 = gsum16(mx.c1);
    float den2 = gsum16(mx.c2), den3 = gsum16(mx.c3);
    mx.m0 = w00/fmaxf(den0,EPSF); mx.m1 = w01/fmaxf(den1,EPSF);
    mx.m2 = w10/fmaxf(den2,EPSF); mx.m3 = w11/fmaxf(den3,EPSF);
    mx.s_k = mx.m0*den0 + mx.m1*den1 + mx.m2*den2 + mx.m3*den3;
    return mx;
}

// ---------------- small kernels ----------------
__global__ void zero_kernel(){
    int t = threadIdx.x;
    if (t < 34) g_mom[t] = 0.0;
    if (t < CC) { g_zs1[t]=0.0; g_zs2[t]=0.0; }
}

__global__ __launch_bounds__(256) void moments_kernel(const float* __restrict__ nxyz,
                                                      const float* __restrict__ cxyz){
    __shared__ double smom[34];
    int tid = threadIdx.x;
    if (tid < 34) smom[tid] = 0.0;
    __syncthreads();
    int p = blockIdx.x*256 + tid;
    Geo g = geom(nxyz, cxyz, p);
    float fc[4] = {g.dx, g.dy, g.dz, g.r};
    float fp[5] = {g.rn, g.sth, g.cth, g.sph, g.cph};
    float v[34];
#pragma unroll
    for (int i=0;i<4;i++){
        v[i] = fc[i];
#pragma unroll
        for (int j=i;j<4;j++) v[4 + i*4 - (i*(i-1))/2 + (j-i)] = fc[i]*fc[j];
    }
#pragma unroll
    for (int i=0;i<5;i++){
        v[14+i] = fp[i];
#pragma unroll
        for (int j=i;j<5;j++) v[19 + i*5 - (i*(i-1))/2 + (j-i)] = fp[i]*fp[j];
    }
#pragma unroll
    for (int i=0;i<34;i++){
        float s = wsum32(v[i]);
        if ((tid&31)==0) atomicAdd(&smom[i], (double)s);
    }
    __syncthreads();
    if (tid < 34) atomicAdd(&g_mom[tid], smom[tid]);
}

__global__ void setup_kernel(
    const float* __restrict__ cf_w1, const float* __restrict__ cf_b1,
    const float* __restrict__ cf_g,  const float* __restrict__ cf_be,
    const float* __restrict__ cf_w2, const float* __restrict__ cf_b2,
    const float* __restrict__ pf_w1, const float* __restrict__ pf_b1,
    const float* __restrict__ pf_g,  const float* __restrict__ pf_be,
    const float* __restrict__ pf_w2, const float* __restrict__ pf_b2,
    const float* __restrict__ ac_w,  const float* __restrict__ ac_b,
    const float* __restrict__ ap_w,  const float* __restrict__ ap_b,
    const float* __restrict__ gamma_p,
    const float* __restrict__ ge_w1, const float* __restrict__ ge_b1,
    const float* __restrict__ ge_w2)
{
    __shared__ float sT[CC*CC];
    __shared__ float sv1[CC], sv2[CC];
    int tid = threadIdx.x;
    float gam = gamma_p[0];
    const double inv = 1.0/(double)NPTS;

    if (tid < CC){
        { // cart BN fold
            double mu[4], cov[4][4];
#pragma unroll
            for (int i=0;i<4;i++) mu[i] = g_mom[i]*inv;
#pragma unroll
            for (int i=0;i<4;i++)
#pragma unroll
                for (int j=i;j<4;j++){
                    double c2 = g_mom[4 + i*4 - (i*(i-1))/2 + (j-i)]*inv - mu[i]*mu[j];
                    cov[i][j]=c2; cov[j][i]=c2;
                }
            double w[4], m=(double)cf_b1[tid], vv=0.0;
#pragma unroll
            for (int i=0;i<4;i++){ w[i]=(double)cf_w1[tid*4+i]; m += w[i]*mu[i]; }
#pragma unroll
            for (int i=0;i<4;i++)
#pragma unroll
                for (int j=0;j<4;j++) vv += w[i]*w[j]*cov[i][j];
            double al = (double)cf_g[tid]/sqrt(vv+1e-5);
#pragma unroll
            for (int i=0;i<4;i++) g_WcfT[i*CC+tid] = (float)(w[i]*al);
            g_bcf[tid] = (float)(((double)cf_b1[tid]-m)*al + (double)cf_be[tid]);
        }
        { // polar BN fold
            double mu[5], cov[5][5];
#pragma unroll
            for (int i=0;i<5;i++) mu[i] = g_mom[14+i]*inv;
#pragma unroll
            for (int i=0;i<5;i++)
#pragma unroll
                for (int j=i;j<5;j++){
                    double c2 = g_mom[19 + i*5 - (i*(i-1))/2 + (j-i)]*inv - mu[i]*mu[j];
                    cov[i][j]=c2; cov[j][i]=c2;
                }
            double w[5], m=(double)pf_b1[tid], vv=0.0;
#pragma unroll
            for (int i=0;i<5;i++){ w[i]=(double)pf_w1[tid*5+i]; m += w[i]*mu[i]; }
#pragma unroll
            for (int i=0;i<5;i++)
#pragma unroll
                for (int j=0;j<5;j++) vv += w[i]*w[j]*cov[i][j];
            double al = (double)pf_g[tid]/sqrt(vv+1e-5);
#pragma unroll
            for (int i=0;i<5;i++) g_WpfT[i*CC+tid] = (float)(w[i]*al);
            g_bpf[tid] = (float)(((double)pf_b1[tid]-m)*al + (double)pf_be[tid]);
        }
    }
    // Wmain rows 0-63 (k) = (ge_w1 @ ac_w @ cf_w2) stored [k][c]
    for (int e=tid;e<CC*CC;e+=blockDim.x){
        int m=e>>6, j=e&63; float s=0.f;
        for (int l=0;l<CC;l++) s += ac_w[m*CC+l]*cf_w2[l*CC+j];
        sT[e]=s;
    }
    __syncthreads();
    for (int e=tid;e<CC*CC;e+=blockDim.x){
        int c=e>>6, j=e&63; float s=0.f;
        for (int m=0;m<CC;m++) s += ge_w1[c*CC+m]*sT[m*CC+j];
        g_Wmain[j*CC+c]=s;
    }
    __syncthreads();
    for (int e=tid;e<CC*CC;e+=blockDim.x){
        int m=e>>6, j=e&63; float s=0.f;
        for (int l=0;l<CC;l++) s += ap_w[m*CC+l]*pf_w2[l*CC+j];
        sT[e]=s;
    }
    __syncthreads();
    for (int e=tid;e<CC*CC;e+=blockDim.x){
        int c=e>>6, j=e&63; float s=0.f;
        for (int m=0;m<CC;m++) s += ge_w1[c*CC+m]*sT[m*CC+j];
        g_Wmain[(64+j)*CC+c]=gam*s;
    }
    if (tid < CC){
        float s1 = ac_b[tid] + gam*ap_b[tid];
        for (int j=0;j<CC;j++) s1 += ac_w[tid*CC+j]*cf_b2[j];
        sv1[tid]=s1;
        float s2 = 0.f;
        for (int j=0;j<CC;j++) s2 += ap_w[tid*CC+j]*pf_b2[j];
        sv2[tid]=s2;
    }
    __syncthreads();
    if (tid < CC){
        float bz = ge_b1[tid], bp = 0.f;
        for (int m=0;m<CC;m++){ bz += ge_w1[tid*CC+m]*sv1[m]; bp += ge_w1[tid*CC+m]*sv2[m]; }
        g_bz[tid]=bz; g_bp[tid]=gam*bp;
    }
    __syncthreads();
    // bf16 split weights [c][k]
    for (int e=tid; e<CC*128; e+=blockDim.x){
        int k = e & 127, c = e >> 7;
        float v = g_Wmain[k*CC + c];
        __nv_bfloat16 h = __float2bfloat16_rn(v);
        float rem = v - __bfloat162float(h);
        g_Whi[c*128 + k] = h;
        g_Wlo[c*128 + k] = __float2bfloat16_rn(rem);
    }
    for (int e=tid; e<CC*CC; e+=blockDim.x){
        int j = e & 63, c = e >> 6;
        float v = ge_w2[c*CC + j];
        __nv_bfloat16 h = __float2bfloat16_rn(v);
        float rem = v - __bfloat162float(h);
        g_W2hi[c*64 + j] = h;
        g_W2lo[c*64 + j] = __float2bfloat16_rn(rem);
    }
}

// ---------------- main kernel smem layout (bytes) ----------------
#define HSTR 136   // elems per H row (p-major), 272B, 68 words == 4 mod 32
#define SH_HHI   0          // 128*272 = 34816
#define SH_HLO   34816      // 34816 -> 69632
#define SH_HP    69632      // 64*128*4 = 32768 -> 102400
#define SH_GEO   102400     // 4608 -> 107008
#define SH_CC    107008     // 2048 -> 109056  (reused as stats S1)
#define SH_MM    109056     // 2048 -> 111104  (reused as stats S2)
#define SH_SK    111104     // 512
#define SH_WCF   111616     // 1024
#define SH_WPF   112640     // 1280
#define SH_BCF   113920     // 256
#define SH_BPF   114176     // 256
#define SH_BZ    114432     // 256
#define SH_BP    114688     // 256
#define MAIN_SMEM 114944

__global__ __launch_bounds__(256,1) void main_kernel(const float* __restrict__ nxyz,
                                                     const float* __restrict__ cxyz){
    extern __shared__ char smc[];
    float* sHPf = (float*)(smc + SH_HP);
    float* sGEO = (float*)(smc + SH_GEO);
    float* sCc  = (float*)(smc + SH_CC);
    float* sMm  = (float*)(smc + SH_MM);
    float* sSK  = (float*)(smc + SH_SK);
    float* sWcf = (float*)(smc + SH_WCF);
    float* sWpf = (float*)(smc + SH_WPF);
    float* sbcf = (float*)(smc + SH_BCF);
    float* sbpf = (float*)(smc + SH_BPF);
    float* sbz  = (float*)(smc + SH_BZ);
    float* sbp  = (float*)(smc + SH_BP);
    int tid = threadIdx.x;
    int wid = tid >> 5;
    int lane = tid & 31;

    for (int i=tid;i<4*CC;i+=256) sWcf[i]=g_WcfT[i];
    for (int i=tid;i<5*CC;i+=256) sWpf[i]=g_WpfT[i];
    if (tid < CC){
        sbcf[tid]=g_bcf[tid]; sbpf[tid]=g_bpf[tid];
        sbz[tid]=g_bz[tid];   sbp[tid]=g_bp[tid];
    }
    __syncthreads();

    int p0 = blockIdx.x*128;

    // phase A: geometry + mix coeffs (threads 0-127)
    if (tid < 128){
        Geo g = geom(nxyz, cxyz, p0 + tid);
        Mix mx = make_mix(g);
        sGEO[0*128+tid]=g.dx;  sGEO[1*128+tid]=g.dy;  sGEO[2*128+tid]=g.dz;
        sGEO[3*128+tid]=g.r;   sGEO[4*128+tid]=g.rn;  sGEO[5*128+tid]=g.sth;
        sGEO[6*128+tid]=g.cth; sGEO[7*128+tid]=g.sph; sGEO[8*128+tid]=g.cph;
        sCc[0*128+tid]=mx.c0; sCc[1*128+tid]=mx.c1; sCc[2*128+tid]=mx.c2; sCc[3*128+tid]=mx.c3;
        sMm[0*128+tid]=mx.m0; sMm[1*128+tid]=mx.m1; sMm[2*128+tid]=mx.m2; sMm[3*128+tid]=mx.m3;
        sSK[tid]=mx.s_k;
    }
    __syncthreads();

    // phase B: first layers. point m = tid&127, half jh = (tid>>7)*32
    {
        int m = tid & 127;
        int jh = (tid >> 7) * 32;
        float dx=sGEO[m],     dy=sGEO[128+m], dz=sGEO[256+m], r =sGEO[384+m];
        float rn=sGEO[512+m], st=sGEO[640+m], ct=sGEO[768+m];
        float sp=sGEO[896+m], cp=sGEO[1024+m];
        char* Hhi = smc + SH_HHI;
        char* Hlo = smc + SH_HLO;
#pragma unroll 4
        for (int j=jh; j<jh+32; j+=2){
            float h0 = sbcf[j];
            h0 = fmaf(dx,sWcf[j],h0); h0 = fmaf(dy,sWcf[64+j],h0);
            h0 = fmaf(dz,sWcf[128+j],h0); h0 = fmaf(r,sWcf[192+j],h0);
            h0 = fmaxf(h0,0.f);
            float h1 = sbcf[j+1];
            h1 = fmaf(dx,sWcf[j+1],h1); h1 = fmaf(dy,sWcf[64+j+1],h1);
            h1 = fmaf(dz,sWcf[128+j+1],h1); h1 = fmaf(r,sWcf[192+j+1],h1);
            h1 = fmaxf(h1,0.f);
            uint32_t hp, lp; split2(h0, h1, hp, lp);
            uint32_t off = (uint32_t)(m*HSTR + j)*2;
            *(uint32_t*)(Hhi + off) = hp;
            *(uint32_t*)(Hlo + off) = lp;
            float q0 = sbpf[j];
            q0 = fmaf(rn,sWpf[j],q0); q0 = fmaf(st,sWpf[64+j],q0);
            q0 = fmaf(ct,sWpf[128+j],q0); q0 = fmaf(sp,sWpf[192+j],q0);
            q0 = fmaf(cp,sWpf[256+j],q0);
            sHPf[j*128+m] = fmaxf(q0,0.f);
            float q1 = sbpf[j+1];
            q1 = fmaf(rn,sWpf[j+1],q1); q1 = fmaf(st,sWpf[64+j+1],q1);
            q1 = fmaf(ct,sWpf[128+j+1],q1); q1 = fmaf(sp,sWpf[192+j+1],q1);
            q1 = fmaf(cp,sWpf[256+j+1],q1);
            sHPf[(j+1)*128+m] = fmaxf(q1,0.f);
        }
    }
    __syncthreads();

    // mix: 512 tasks (64 rows x 8 k-groups) over 256 threads
#pragma unroll
    for (int t2i=0;t2i<2;t2i++){
        int tk = t2i*256 + tid;
        int j = tk>>3, grp = tk&7;
        float* hrow = sHPf + j*128 + grp*16;
        const float* cb = sCc + grp*16;
        const float* mb = sMm + grp*16;
        float h[16];
#pragma unroll
        for (int k=0;k<16;k++) h[k]=hrow[k];
        float g0=0.f,g1=0.f,g2=0.f,g3=0.f;
#pragma unroll
        for (int k=0;k<16;k++){
            g0 = fmaf(cb[0*128+k], h[k], g0);
            g1 = fmaf(cb[1*128+k], h[k], g1);
            g2 = fmaf(cb[2*128+k], h[k], g2);
            g3 = fmaf(cb[3*128+k], h[k], g3);
        }
#pragma unroll
        for (int k=0;k<16;k++){
            float o = mb[0*128+k]*g0;
            o = fmaf(mb[1*128+k], g1, o);
            o = fmaf(mb[2*128+k], g2, o);
            o = fmaf(mb[3*128+k], g3, o);
            hrow[k] = o;
        }
    }
    __syncthreads();

    // convert polar to bf16 H cols 64..127; zero stats staging
    {
        int m = tid & 127;
        int ch = (tid >> 7) * 32;
        char* Hhi = smc + SH_HHI;
        char* Hlo = smc + SH_HLO;
#pragma unroll 4
        for (int jj=ch; jj<ch+32; jj+=2){
            float v0 = sHPf[jj*128+m];
            float v1 = sHPf[(jj+1)*128+m];
            uint32_t hp, lp; split2(v0, v1, hp, lp);
            uint32_t off = (uint32_t)(m*HSTR + 64 + jj)*2;
            *(uint32_t*)(Hhi + off) = hp;
            *(uint32_t*)(Hlo + off) = lp;
        }
    }
    if (tid < CC){ sCc[tid]=0.f; sMm[tid]=0.f; }
    __syncthreads();

    // GEMM via mma.sync bf16, 3-pass split
    {
        int g = lane >> 2;
        int t2 = (lane & 3) * 2;
        int c0 = (wid & 3) * 16;
        int ph = (wid >> 2) * 64;
        int r0 = c0 + g, r1 = c0 + g + 8;

        uint32_t Ah[8][4], Al[8][4];
        const uint16_t* Wh = (const uint16_t*)g_Whi;
        const uint16_t* Wl = (const uint16_t*)g_Wlo;
#pragma unroll
        for (int ks=0; ks<8; ks++){
            int kb = ks*16;
            Ah[ks][0] = *(const uint32_t*)(Wh + r0*128 + kb + t2);
            Ah[ks][1] = *(const uint32_t*)(Wh + r1*128 + kb + t2);
            Ah[ks][2] = *(const uint32_t*)(Wh + r0*128 + kb + 8 + t2);
            Ah[ks][3] = *(const uint32_t*)(Wh + r1*128 + kb + 8 + t2);
            Al[ks][0] = *(const uint32_t*)(Wl + r0*128 + kb + t2);
            Al[ks][1] = *(const uint32_t*)(Wl + r1*128 + kb + t2);
            Al[ks][2] = *(const uint32_t*)(Wl + r0*128 + kb + 8 + t2);
            Al[ks][3] = *(const uint32_t*)(Wl + r1*128 + kb + 8 + t2);
        }
        const uint16_t* Hh = (const uint16_t*)(smc + SH_HHI);
        const uint16_t* Hl = (const uint16_t*)(smc + SH_HLO);
        float bz0 = sbz[r0], bz1 = sbz[r1], bp0 = sbp[r0], bp1 = sbp[r1];
        float s10=0.f, s20=0.f, s11=0.f, s21=0.f;
#pragma unroll 1
        for (int nt=0; nt<8; nt++){
            int pn = ph + nt*8;
            const uint16_t* hb = Hh + (pn + g)*HSTR;
            const uint16_t* lb = Hl + (pn + g)*HSTR;
            float a0=0.f, a1=0.f, a2=0.f, a3=0.f;
#pragma unroll
            for (int ks=0; ks<8; ks++){
                int kb = ks*16 + t2;
                uint32_t bh0 = *(const uint32_t*)(hb + kb);
                uint32_t bh1 = *(const uint32_t*)(hb + kb + 8);
                uint32_t bl0 = *(const uint32_t*)(lb + kb);
                uint32_t bl1 = *(const uint32_t*)(lb + kb + 8);
                MMA_BF16(a0,a1,a2,a3, Ah[ks][0],Ah[ks][1],Ah[ks][2],Ah[ks][3], bh0,bh1);
                MMA_BF16(a0,a1,a2,a3, Ah[ks][0],Ah[ks][1],Ah[ks][2],Ah[ks][3], bl0,bl1);
                MMA_BF16(a0,a1,a2,a3, Al[ks][0],Al[ks][1],Al[ks][2],Al[ks][3], bh0,bh1);
            }
            int col = pn + t2;
            float sk0 = sSK[col], sk1 = sSK[col+1];
            float z00 = a0 + fmaf(bp0, sk0, bz0);
            float z01 = a1 + fmaf(bp0, sk1, bz0);
            float z10 = a2 + fmaf(bp1, sk0, bz1);
            float z11 = a3 + fmaf(bp1, sk1, bz1);
            *(float2*)(g_z1 + (size_t)r0*NPTS + p0 + col) = make_float2(z00,z01);
            *(float2*)(g_z1 + (size_t)r1*NPTS + p0 + col) = make_float2(z10,z11);
            s10 += z00+z01; s20 += z00*z00+z01*z01;
            s11 += z10+z11; s21 += z10*z10+z11*z11;
        }
        s10 += __shfl_xor_sync(0xffffffffu, s10, 1); s10 += __shfl_xor_sync(0xffffffffu, s10, 2);
        s20 += __shfl_xor_sync(0xffffffffu, s20, 1); s20 += __shfl_xor_sync(0xffffffffu, s20, 2);
        s11 += __shfl_xor_sync(0xffffffffu, s11, 1); s11 += __shfl_xor_sync(0xffffffffu, s11, 2);
        s21 += __shfl_xor_sync(0xffffffffu, s21, 1); s21 += __shfl_xor_sync(0xffffffffu, s21, 2);
        if ((lane & 3) == 0){
            atomicAdd(&sCc[r0], s10); atomicAdd(&sMm[r0], s20);
            atomicAdd(&sCc[r1], s11); atomicAdd(&sMm[r1], s21);
        }
    }
    __syncthreads();
    if (tid < CC){
        atomicAdd(&g_zs1[tid], (double)sCc[tid]);
        atomicAdd(&g_zs2[tid], (double)sMm[tid]);
    }
}

__global__ void bnstats_kernel(const float* __restrict__ ge_g, const float* __restrict__ ge_be){
    int c = threadIdx.x;
    if (c < CC){
        double mean = g_zs1[c]/(double)NPTS;
        double var  = g_zs2[c]/(double)NPTS - mean*mean;
        double a = (double)ge_g[c]/sqrt(var + 1e-5);
        g_alpha[c] = (float)a;
        g_beta[c]  = (float)((double)ge_be[c] - mean*a);
    }
}

// ---------------- final kernel ----------------
#define FSTR 72    // elems per H2 row, 144B, 36 words == 4 mod 32
#define FH_HHI 0        // 128*144 = 18432
#define FH_HLO 18432    // -> 36864
#define FH_A   36864    // 256
#define FH_BV  37120    // 256
#define FH_B2  37376    // 256
#define FINAL_SMEM 37632

__global__ __launch_bounds__(256,2) void final_kernel(const float* __restrict__ ge_b2,
                                                      float* __restrict__ out){
    extern __shared__ char smc[];
    float* sa  = (float*)(smc + FH_A);
    float* sbv = (float*)(smc + FH_BV);
    float* sb2 = (float*)(smc + FH_B2);
    int tid = threadIdx.x;
    int wid = tid >> 5;
    int lane = tid & 31;

    if (tid < CC){ sa[tid]=g_alpha[tid]; sbv[tid]=g_beta[tid]; sb2[tid]=ge_b2[tid]; }
    __syncthreads();

    int p0 = blockIdx.x*128;

    // phase 1: load z, affine+relu, bf16 split -> H2[p][c]
    {
        int m = tid & 127;
        int ch = (tid >> 7) * 32;
        char* Hhi = smc + FH_HHI;
        char* Hlo = smc + FH_HLO;
#pragma unroll 4
        for (int c=ch; c<ch+32; c+=2){
            float z0 = g_z1[(size_t)c*NPTS + p0 + m];
            float z1v = g_z1[(size_t)(c+1)*NPTS + p0 + m];
            float h0 = fmaxf(fmaf(z0, sa[c], sbv[c]), 0.f);
            float h1 = fmaxf(fmaf(z1v, sa[c+1], sbv[c+1]), 0.f);
            uint32_t hp, lp; split2(h0, h1, hp, lp);
            uint32_t off = (uint32_t)(m*FSTR + c)*2;
            *(uint32_t*)(Hhi + off) = hp;
            *(uint32_t*)(Hlo + off) = lp;
        }
    }
    __syncthreads();

    {
        int g = lane >> 2;
        int t2 = (lane & 3) * 2;
        int c0 = (wid & 3) * 16;
        int ph = (wid >> 2) * 64;
        int r0 = c0 + g, r1 = c0 + g + 8;

        uint32_t Ah[4][4], Al[4][4];
        const uint16_t* Wh = (const uint16_t*)g_W2hi;
        const uint16_t* Wl = (const uint16_t*)g_W2lo;
#pragma unroll
        for (int ks=0; ks<4; ks++){
            int kb = ks*16;
            Ah[ks][0] = *(const uint32_t*)(Wh + r0*64 + kb + t2);
            Ah[ks][1] = *(const uint32_t*)(Wh + r1*64 + kb + t2);
            Ah[ks][2] = *(const uint32_t*)(Wh + r0*64 + kb + 8 + t2);
            Ah[ks][3] = *(const uint32_t*)(Wh + r1*64 + kb + 8 + t2);
            Al[ks][0] = *(const uint32_t*)(Wl + r0*64 + kb + t2);
            Al[ks][1] = *(const uint32_t*)(Wl + r1*64 + kb + t2);
            Al[ks][2] = *(const uint32_t*)(Wl + r0*64 + kb + 8 + t2);
            Al[ks][3] = *(const uint32_t*)(Wl + r1*64 + kb + 8 + t2);
        }
        const uint16_t* Hh = (const uint16_t*)(smc + FH_HHI);
        const uint16_t* Hl = (const uint16_t*)(smc + FH_HLO);
        float b0v = sb2[r0], b1v = sb2[r1];
        int b = p0 >> 16;
        int nk0 = p0 & 65535;
        float* ob = out + (size_t)b*CC*65536;
#pragma unroll 1
        for (int nt=0; nt<8; nt++){
            int pn = ph + nt*8;
            const uint16_t* hb = Hh + (pn + g)*FSTR;
            const uint16_t* lb = Hl + (pn + g)*FSTR;
            float a0=0.f, a1=0.f, a2=0.f, a3=0.f;
#pragma unroll
            for (int ks=0; ks<4; ks++){
                int kb = ks*16 + t2;
                uint32_t bh0 = *(const uint32_t*)(hb + kb);
                uint32_t bh1 = *(const uint32_t*)(hb + kb + 8);
                uint32_t bl0 = *(const uint32_t*)(lb + kb);
                uint32_t bl1 = *(const uint32_t*)(lb + kb + 8);
                MMA_BF16(a0,a1,a2,a3, Ah[ks][0],Ah[ks][1],Ah[ks][2],Ah[ks][3], bh0,bh1);
                MMA_BF16(a0,a1,a2,a3, Ah[ks][0],Ah[ks][1],Ah[ks][2],Ah[ks][3], bl0,bl1);
                MMA_BF16(a0,a1,a2,a3, Al[ks][0],Al[ks][1],Al[ks][2],Al[ks][3], bh0,bh1);
            }
            int col = pn + t2;
            *(float2*)(ob + (size_t)r0*65536 + nk0 + col) = make_float2(a0+b0v, a1+b0v);
            *(float2*)(ob + (size_t)r1*65536 + nk0 + col) = make_float2(a2+b1v, a3+b1v);
        }
    }
}

extern "C" void kernel_launch(void* const* d_in, const int* in_sizes, int n_in,
                              void* d_out, int out_size){
    const float* nxyz  = (const float*)d_in[0];
    const float* cxyz  = (const float*)d_in[1];
    const float* cf_w1 = (const float*)d_in[2];
    const float* cf_b1 = (const float*)d_in[3];
    const float* cf_g  = (const float*)d_in[4];
    const float* cf_be = (const float*)d_in[5];
    const float* cf_w2 = (const float*)d_in[6];
    const float* cf_b2 = (const float*)d_in[7];
    const float* pf_w1 = (const float*)d_in[8];
    const float* pf_b1 = (const float*)d_in[9];
    const float* pf_g  = (const float*)d_in[10];
    const float* pf_be = (const float*)d_in[11];
    const float* pf_w2 = (const float*)d_in[12];
    const float* pf_b2 = (const float*)d_in[13];
    const float* ac_w  = (const float*)d_in[14];
    const float* ac_b  = (const float*)d_in[15];
    const float* ap_w  = (const float*)d_in[16];
    const float* ap_b  = (const float*)d_in[17];
    const float* gamma = (const float*)d_in[18];
    const float* ge_w1 = (const float*)d_in[19];
    const float* ge_b1 = (const float*)d_in[20];
    const float* ge_g  = (const float*)d_in[21];
    const float* ge_be = (const float*)d_in[22];
    const float* ge_w2 = (const float*)d_in[23];
    const float* ge_b2 = (const float*)d_in[24];
    float* out = (float*)d_out;

    cudaFuncSetAttribute(main_kernel, cudaFuncAttributeMaxDynamicSharedMemorySize, MAIN_SMEM);
    cudaFuncSetAttribute(final_kernel, cudaFuncAttributeMaxDynamicSharedMemorySize, FINAL_SMEM);

    zero_kernel<<<1, 64>>>();
    moments_kernel<<<NPTS/256, 256>>>(nxyz, cxyz);
    setup_kernel<<<1, 256>>>(cf_w1, cf_b1, cf_g, cf_be, cf_w2, cf_b2,
                             pf_w1, pf_b1, pf_g, pf_be, pf_w2, pf_b2,
                             ac_w, ac_b, ap_w, ap_b, gamma,
                             ge_w1, ge_b1, ge_w2);
    main_kernel<<<NPTS/128, 256, MAIN_SMEM>>>(nxyz, cxyz);
    bnstats_kernel<<<1, 64>>>(ge_g, ge_be);
    final_kernel<<<NPTS/128, 256, FINAL_SMEM>>>(ge_b2, out);
}